// round 1
// baseline (speedup 1.0000x reference)
#include <cuda_runtime.h>
#include <cstdint>

#define D_  1024
#define H_  16
#define HD_ 64
#define T_  1024
#define B_  2
#define L_  8
#define FF_ 4096
#define V_  32000
#define M_  (B_ * T_)   // 2048 rows

// ---------------- scratch (device globals: no allocations allowed) ----------
__device__ float g_x [M_ * D_];
__device__ float g_h [M_ * D_];
__device__ float g_q [M_ * D_];
__device__ float g_k [M_ * D_];
__device__ float g_v [M_ * D_];
__device__ float g_o [M_ * D_];
__device__ float g_ff[M_ * FF_];
__device__ float g_hf[B_ * D_];

// ---------------- embedding: x = tok_emb[idx] + pos_emb ---------------------
__global__ void embed_k(const int* __restrict__ idx,
                        const float* __restrict__ tok,
                        const float* __restrict__ pos) {
    int m = blockIdx.x;                 // 0..2047  (b*T + t)
    int t = m & (T_ - 1);
    const float* te = tok + (size_t)idx[m] * D_;
    const float* pe = pos + (size_t)t * D_;
    float* xr = g_x + (size_t)m * D_;
    for (int d = threadIdx.x; d < D_; d += blockDim.x)
        xr[d] = te[d] + pe[d];
}

// ---------------- layernorm: one block (256 thr) per row --------------------
__global__ void ln_k(const float* __restrict__ in, long in_stride,
                     const float* __restrict__ w, const float* __restrict__ b,
                     float* __restrict__ out, long out_stride) {
    const float* row = in + (size_t)blockIdx.x * in_stride;
    float* orow = out + (size_t)blockIdx.x * out_stride;
    int tid = threadIdx.x;
    float vals[4];
    float s = 0.f;
    #pragma unroll
    for (int i = 0; i < 4; i++) { vals[i] = row[tid + 256 * i]; s += vals[i]; }

    __shared__ float red[8];
    int lane = tid & 31, warp = tid >> 5;
    #pragma unroll
    for (int off = 16; off; off >>= 1) s += __shfl_xor_sync(0xffffffffu, s, off);
    if (lane == 0) red[warp] = s;
    __syncthreads();
    float tot = 0.f;
    #pragma unroll
    for (int i = 0; i < 8; i++) tot += red[i];
    float mean = tot * (1.0f / D_);

    float s2 = 0.f;
    #pragma unroll
    for (int i = 0; i < 4; i++) { float d = vals[i] - mean; s2 += d * d; }
    __syncthreads();
    #pragma unroll
    for (int off = 16; off; off >>= 1) s2 += __shfl_xor_sync(0xffffffffu, s2, off);
    if (lane == 0) red[warp] = s2;
    __syncthreads();
    float tot2 = 0.f;
    #pragma unroll
    for (int i = 0; i < 8; i++) tot2 += red[i];
    float inv = rsqrtf(tot2 * (1.0f / D_) + 1e-5f);

    #pragma unroll
    for (int i = 0; i < 4; i++) {
        int d = tid + 256 * i;
        orow[d] = (vals[i] - mean) * inv * w[d] + b[d];
    }
}

// ---------------- tiled SGEMM: C[M,N] = A[M,K] @ W[K,N] + bias (+res)(relu) --
// BM=BN=64, BK=16, 256 threads, 4x4 per thread.
// QKV==true: write C to [B,H,T,HD] layout (m=b*T+t, n=h*HD+hd).
template<bool RELU, bool QKV, bool RES>
__global__ __launch_bounds__(256)
void gemm_k(const float* __restrict__ A, const float* __restrict__ W,
            const float* __restrict__ bias, const float* __restrict__ res,
            float* __restrict__ C, int Mdim, int Ndim, int Kdim) {
    __shared__ float As[16][64];
    __shared__ float Bs[16][64];
    const int bn = blockIdx.x * 64;
    const int bm = blockIdx.y * 64;
    const int tx = threadIdx.x & 15;
    const int ty = threadIdx.x >> 4;

    const int aRow = threadIdx.x >> 2;          // 0..63
    const int aK4  = (threadIdx.x & 3) * 4;     // 0,4,8,12
    const int bK   = threadIdx.x >> 4;          // 0..15
    const int bN4  = (threadIdx.x & 15) * 4;

    float acc[4][4] = {};

    const float* Ap = A + (size_t)(bm + aRow) * Kdim + aK4;
    const float* Wp = W + (size_t)bK * Ndim + bn + bN4;

    for (int k0 = 0; k0 < Kdim; k0 += 16) {
        float4 a = *(const float4*)(Ap + k0);
        As[aK4 + 0][aRow] = a.x;
        As[aK4 + 1][aRow] = a.y;
        As[aK4 + 2][aRow] = a.z;
        As[aK4 + 3][aRow] = a.w;
        *(float4*)&Bs[bK][bN4] = *(const float4*)(Wp + (size_t)k0 * Ndim);
        __syncthreads();
        #pragma unroll
        for (int kk = 0; kk < 16; kk++) {
            float4 av = *(const float4*)&As[kk][ty * 4];
            float4 bv = *(const float4*)&Bs[kk][tx * 4];
            acc[0][0] += av.x * bv.x; acc[0][1] += av.x * bv.y;
            acc[0][2] += av.x * bv.z; acc[0][3] += av.x * bv.w;
            acc[1][0] += av.y * bv.x; acc[1][1] += av.y * bv.y;
            acc[1][2] += av.y * bv.z; acc[1][3] += av.y * bv.w;
            acc[2][0] += av.z * bv.x; acc[2][1] += av.z * bv.y;
            acc[2][2] += av.z * bv.z; acc[2][3] += av.z * bv.w;
            acc[3][0] += av.w * bv.x; acc[3][1] += av.w * bv.y;
            acc[3][2] += av.w * bv.z; acc[3][3] += av.w * bv.w;
        }
        __syncthreads();
    }

    #pragma unroll
    for (int i = 0; i < 4; i++) {
        int m = bm + ty * 4 + i;
        #pragma unroll
        for (int j = 0; j < 4; j++) {
            int n = bn + tx * 4 + j;
            float v = acc[i][j] + bias[n];
            if (RES) v += res[(size_t)m * Ndim + n];
            if (RELU) v = fmaxf(v, 0.0f);
            size_t oidx;
            if (QKV) {
                int b = m >> 10, t = m & (T_ - 1);
                int h = n >> 6,  hd = n & (HD_ - 1);
                oidx = ((size_t)(b * H_ + h) * T_ + t) * HD_ + hd;
            } else {
                oidx = (size_t)m * Ndim + n;
            }
            C[oidx] = v;
        }
    }
}

// ---------------- flash attention: warp per query, 8 warps/block ------------
__global__ __launch_bounds__(256)
void attn_k(const float* __restrict__ q, const float* __restrict__ k,
            const float* __restrict__ v, float* __restrict__ o) {
    int bh   = blockIdx.y;                   // 0..31  (b*H + h)
    int warp = threadIdx.x >> 5;             // 0..7
    int lane = threadIdx.x & 31;
    int qi   = blockIdx.x * 8 + warp;        // query row 0..1023
    int b = bh >> 4, h = bh & 15;

    const float* qp = q + ((size_t)bh * T_ + qi) * HD_;
    const float* kb = k + (size_t)bh * T_ * HD_;
    const float* vb = v + (size_t)bh * T_ * HD_;

    float q0 = qp[lane], q1 = qp[lane + 32];
    float mx = -1e30f, l = 0.f, o0 = 0.f, o1 = 0.f;
    const float scale = 0.125f;   // 1/sqrt(64)

    for (int j = 0; j <= qi; j++) {
        const float* kp = kb + (size_t)j * HD_;
        float p = q0 * kp[lane] + q1 * kp[lane + 32];
        #pragma unroll
        for (int off = 16; off; off >>= 1) p += __shfl_xor_sync(0xffffffffu, p, off);
        p *= scale;
        float mn   = fmaxf(mx, p);
        float corr = __expf(mx - mn);
        float e    = __expf(p - mn);
        l = l * corr + e;
        const float* vp = vb + (size_t)j * HD_;
        o0 = o0 * corr + e * vp[lane];
        o1 = o1 * corr + e * vp[lane + 32];
        mx = mn;
    }
    float invl = 1.0f / l;
    float* op = o + ((size_t)(b * T_ + qi)) * D_ + h * HD_;
    op[lane]      = o0 * invl;
    op[lane + 32] = o1 * invl;
}

// ---------------- head GEMV: logits[b,v] = hf[b] . head_w[:,v] + head_b -----
__global__ __launch_bounds__(256)
void head_k(const float* __restrict__ hf, const float* __restrict__ W,
            const float* __restrict__ hb, float* __restrict__ out) {
    __shared__ float s0[D_];
    __shared__ float s1[D_];
    for (int i = threadIdx.x; i < D_; i += 256) { s0[i] = hf[i]; s1[i] = hf[D_ + i]; }
    __syncthreads();
    int vcol = blockIdx.x * 256 + threadIdx.x;
    float a0 = 0.f, a1 = 0.f;
    #pragma unroll 4
    for (int d = 0; d < D_; d++) {
        float wv = W[(size_t)d * V_ + vcol];
        a0 += s0[d] * wv;
        a1 += s1[d] * wv;
    }
    float bb = hb[vcol];
    out[vcol]      = a0 + bb;
    out[V_ + vcol] = a1 + bb;
}

// ---------------- launch --------------------------------------------------
extern "C" void kernel_launch(void* const* d_in, const int* in_sizes, int n_in,
                              void* d_out, int out_size) {
    const int*   idx    = (const int*)  d_in[0];
    const float* tok    = (const float*)d_in[1];
    const float* pos    = (const float*)d_in[2];
    const float* ln1w   = (const float*)d_in[3];
    const float* ln1b   = (const float*)d_in[4];
    const float* qw     = (const float*)d_in[5];
    const float* qb     = (const float*)d_in[6];
    const float* kw     = (const float*)d_in[7];
    const float* kb     = (const float*)d_in[8];
    const float* vw     = (const float*)d_in[9];
    const float* vb     = (const float*)d_in[10];
    const float* ow     = (const float*)d_in[11];
    const float* ob     = (const float*)d_in[12];
    const float* ln2w   = (const float*)d_in[13];
    const float* ln2b   = (const float*)d_in[14];
    const float* f1w    = (const float*)d_in[15];
    const float* f1b    = (const float*)d_in[16];
    const float* f2w    = (const float*)d_in[17];
    const float* f2b    = (const float*)d_in[18];
    const float* lnfw   = (const float*)d_in[19];
    const float* lnfb   = (const float*)d_in[20];
    const float* headw  = (const float*)d_in[21];
    const float* headb  = (const float*)d_in[22];

    float *x, *h, *q, *k, *v, *o, *ff, *hf;
    cudaGetSymbolAddress((void**)&x,  g_x);
    cudaGetSymbolAddress((void**)&h,  g_h);
    cudaGetSymbolAddress((void**)&q,  g_q);
    cudaGetSymbolAddress((void**)&k,  g_k);
    cudaGetSymbolAddress((void**)&v,  g_v);
    cudaGetSymbolAddress((void**)&o,  g_o);
    cudaGetSymbolAddress((void**)&ff, g_ff);
    cudaGetSymbolAddress((void**)&hf, g_hf);

    embed_k<<<M_, 256>>>(idx, tok, pos);

    dim3 gDD(D_ / 64, M_ / 64);    // (16, 32)
    dim3 gDF(FF_ / 64, M_ / 64);   // (64, 32)
    dim3 gAt(T_ / 8, B_ * H_);     // (128, 32)

    for (int l = 0; l < L_; l++) {
        size_t wDD = (size_t)l * D_ * D_;
        size_t wDF = (size_t)l * D_ * FF_;

        ln_k<<<M_, 256>>>(x, D_, ln1w + l * D_, ln1b + l * D_, h, D_);

        gemm_k<false, true,  false><<<gDD, 256>>>(h, qw + wDD, qb + l * D_, nullptr, q, M_, D_, D_);
        gemm_k<false, true,  false><<<gDD, 256>>>(h, kw + wDD, kb + l * D_, nullptr, k, M_, D_, D_);
        gemm_k<false, true,  false><<<gDD, 256>>>(h, vw + wDD, vb + l * D_, nullptr, v, M_, D_, D_);

        attn_k<<<gAt, 256>>>(q, k, v, o);

        gemm_k<false, false, true ><<<gDD, 256>>>(o, ow + wDD, ob + l * D_, x, x, M_, D_, D_);

        ln_k<<<M_, 256>>>(x, D_, ln2w + l * D_, ln2b + l * D_, h, D_);

        gemm_k<true,  false, false><<<gDF, 256>>>(h,  f1w + wDF, f1b + l * FF_, nullptr, ff, M_, FF_, D_);
        gemm_k<false, false, true ><<<gDD, 256>>>(ff, f2w + wDF, f2b + l * D_,  x,       x,  M_, D_, FF_);
    }

    // final LN on the two last-token rows only
    ln_k<<<B_, 256>>>(x + (size_t)(T_ - 1) * D_, (long)T_ * D_, lnfw, lnfb, hf, D_);

    head_k<<<V_ / 256, 256>>>(hf, headw, headb, (float*)d_out);
}

// round 2
// speedup vs baseline: 1.5595x; 1.5595x over previous
#include <cuda_runtime.h>
#include <cstdint>

#define D_  1024
#define H_  16
#define HD_ 64
#define T_  1024
#define B_  2
#define L_  8
#define FF_ 4096
#define V_  32000
#define M_  (B_ * T_)   // 2048 rows

// ---------------- scratch (device globals: no allocations allowed) ----------
__device__ float g_x [M_ * D_];
__device__ float g_h [M_ * D_];
__device__ float g_q [M_ * D_];
__device__ float g_k [M_ * D_];
__device__ float g_v [M_ * D_];
__device__ float g_o [M_ * D_];
__device__ float g_ff[M_ * FF_];
__device__ float g_hf[B_ * D_];

// ---------------- embedding: x = tok_emb[idx] + pos_emb ---------------------
__global__ void embed_k(const int* __restrict__ idx,
                        const float* __restrict__ tok,
                        const float* __restrict__ pos) {
    int m = blockIdx.x;
    int t = m & (T_ - 1);
    const float* te = tok + (size_t)idx[m] * D_;
    const float* pe = pos + (size_t)t * D_;
    float* xr = g_x + (size_t)m * D_;
    for (int d = threadIdx.x; d < D_; d += blockDim.x)
        xr[d] = te[d] + pe[d];
}

// ---------------- layernorm: one block (256 thr) per row --------------------
__global__ void ln_k(const float* __restrict__ in, long in_stride,
                     const float* __restrict__ w, const float* __restrict__ b,
                     float* __restrict__ out, long out_stride) {
    const float* row = in + (size_t)blockIdx.x * in_stride;
    float* orow = out + (size_t)blockIdx.x * out_stride;
    int tid = threadIdx.x;
    float vals[4];
    float s = 0.f;
    #pragma unroll
    for (int i = 0; i < 4; i++) { vals[i] = row[tid + 256 * i]; s += vals[i]; }

    __shared__ float red[8];
    int lane = tid & 31, warp = tid >> 5;
    #pragma unroll
    for (int off = 16; off; off >>= 1) s += __shfl_xor_sync(0xffffffffu, s, off);
    if (lane == 0) red[warp] = s;
    __syncthreads();
    float tot = 0.f;
    #pragma unroll
    for (int i = 0; i < 8; i++) tot += red[i];
    float mean = tot * (1.0f / D_);

    float s2 = 0.f;
    #pragma unroll
    for (int i = 0; i < 4; i++) { float d = vals[i] - mean; s2 += d * d; }
    __syncthreads();
    #pragma unroll
    for (int off = 16; off; off >>= 1) s2 += __shfl_xor_sync(0xffffffffu, s2, off);
    if (lane == 0) red[warp] = s2;
    __syncthreads();
    float tot2 = 0.f;
    #pragma unroll
    for (int i = 0; i < 8; i++) tot2 += red[i];
    float inv = rsqrtf(tot2 * (1.0f / D_) + 1e-5f);

    #pragma unroll
    for (int i = 0; i < 4; i++) {
        int d = tid + 256 * i;
        orow[d] = (vals[i] - mean) * inv * w[d] + b[d];
    }
}

// ---------------- 128x128x16 SGEMM, 8x8/thread, split fragments --------------
// C[M,N] = A[M,K] @ W[K,N] + bias (+res)(relu). QKV: permute out to [B,H,T,HD].
template<bool RELU, bool QKV, bool RES>
__global__ __launch_bounds__(256, 2)
void gemm_k(const float* __restrict__ A, const float* __restrict__ W,
            const float* __restrict__ bias, const float* __restrict__ res,
            float* __restrict__ C, int Ndim, int Kdim) {
    __shared__ float As[16][132];   // padded: 2-way-max STS conflicts
    __shared__ float Bs[16][128];

    const int t  = threadIdx.x;
    const int bn = blockIdx.x * 128;
    const int bm = blockIdx.y * 128;
    const int tx = t & 15;          // col fragment selector
    const int ty = t >> 4;          // row fragment selector

    // A-tile load mapping: 4 lanes per row, rows t>>2 and t>>2+64
    const int aRow = t >> 2;              // 0..63
    const int aK4  = (t & 3) * 4;         // 0,4,8,12
    // B-tile load mapping
    const int bK   = t >> 5;              // 0..7 (two loads: +8)
    const int bN4  = (t & 31) * 4;

    const float* Ap0 = A + (size_t)(bm + aRow)      * Kdim + aK4;
    const float* Ap1 = A + (size_t)(bm + aRow + 64) * Kdim + aK4;
    const float* Wp0 = W + (size_t)bK       * Ndim + bn + bN4;
    const float* Wp1 = W + (size_t)(bK + 8) * Ndim + bn + bN4;

    float acc[8][8] = {};

    float4 pa0 = *(const float4*)(Ap0);
    float4 pa1 = *(const float4*)(Ap1);
    float4 pb0 = *(const float4*)(Wp0);
    float4 pb1 = *(const float4*)(Wp1);

    for (int k0 = 0; k0 < Kdim; k0 += 16) {
        // commit prefetched tile to smem
        As[aK4 + 0][aRow] = pa0.x; As[aK4 + 1][aRow] = pa0.y;
        As[aK4 + 2][aRow] = pa0.z; As[aK4 + 3][aRow] = pa0.w;
        As[aK4 + 0][aRow + 64] = pa1.x; As[aK4 + 1][aRow + 64] = pa1.y;
        As[aK4 + 2][aRow + 64] = pa1.z; As[aK4 + 3][aRow + 64] = pa1.w;
        *(float4*)&Bs[bK][bN4]     = pb0;
        *(float4*)&Bs[bK + 8][bN4] = pb1;
        __syncthreads();

        if (k0 + 16 < Kdim) {
            pa0 = *(const float4*)(Ap0 + k0 + 16);
            pa1 = *(const float4*)(Ap1 + k0 + 16);
            pb0 = *(const float4*)(Wp0 + (size_t)(k0 + 16) * Ndim);
            pb1 = *(const float4*)(Wp1 + (size_t)(k0 + 16) * Ndim);
        }

        #pragma unroll
        for (int kk = 0; kk < 16; kk++) {
            float4 a0 = *(const float4*)&As[kk][ty * 4];
            float4 a1 = *(const float4*)&As[kk][64 + ty * 4];
            float4 b0 = *(const float4*)&Bs[kk][tx * 4];
            float4 b1 = *(const float4*)&Bs[kk][64 + tx * 4];
            float av[8] = {a0.x, a0.y, a0.z, a0.w, a1.x, a1.y, a1.z, a1.w};
            float bv[8] = {b0.x, b0.y, b0.z, b0.w, b1.x, b1.y, b1.z, b1.w};
            #pragma unroll
            for (int i = 0; i < 8; i++)
                #pragma unroll
                for (int j = 0; j < 8; j++)
                    acc[i][j] += av[i] * bv[j];
        }
        __syncthreads();
    }

    // epilogue: rows bm + ig*64 + ty*4 + ii, cols bn + jg*64 + tx*4 (+0..3)
    #pragma unroll
    for (int ig = 0; ig < 2; ig++) {
        #pragma unroll
        for (int ii = 0; ii < 4; ii++) {
            int m = bm + ig * 64 + ty * 4 + ii;
            #pragma unroll
            for (int jg = 0; jg < 2; jg++) {
                int n = bn + jg * 64 + tx * 4;
                float4 vv;
                vv.x = acc[ig * 4 + ii][jg * 4 + 0] + bias[n + 0];
                vv.y = acc[ig * 4 + ii][jg * 4 + 1] + bias[n + 1];
                vv.z = acc[ig * 4 + ii][jg * 4 + 2] + bias[n + 2];
                vv.w = acc[ig * 4 + ii][jg * 4 + 3] + bias[n + 3];
                if (RES) {
                    const float4 rr = *(const float4*)(res + (size_t)m * Ndim + n);
                    vv.x += rr.x; vv.y += rr.y; vv.z += rr.z; vv.w += rr.w;
                }
                if (RELU) {
                    vv.x = fmaxf(vv.x, 0.f); vv.y = fmaxf(vv.y, 0.f);
                    vv.z = fmaxf(vv.z, 0.f); vv.w = fmaxf(vv.w, 0.f);
                }
                size_t oidx;
                if (QKV) {
                    int b = m >> 10, tt = m & (T_ - 1);
                    int h = n >> 6,  hd = n & (HD_ - 1);
                    oidx = ((size_t)(b * H_ + h) * T_ + tt) * HD_ + hd;
                } else {
                    oidx = (size_t)m * Ndim + n;
                }
                *(float4*)(C + oidx) = vv;
            }
        }
    }
}

// ---------------- tiled flash attention: 8 queries/block, 64-key tiles ------
__global__ __launch_bounds__(256)
void attn_k(const float* __restrict__ q, const float* __restrict__ k,
            const float* __restrict__ v, float* __restrict__ o) {
    __shared__ float Ks[64][68];
    __shared__ float Vs[64][68];
    __shared__ float qs[8][64];

    int bh   = blockIdx.y;                   // b*H + h
    int warp = threadIdx.x >> 5;
    int lane = threadIdx.x & 31;
    int qi   = blockIdx.x * 8 + warp;
    int b = bh >> 4, h = bh & 15;

    const float* kb = k + (size_t)bh * T_ * HD_;
    const float* vb = v + (size_t)bh * T_ * HD_;
    const float* qp = q + ((size_t)bh * T_ + qi) * HD_;
    qs[warp][lane]      = qp[lane];
    qs[warp][lane + 32] = qp[lane + 32];

    float mx = -1e30f, l = 0.f, o0 = 0.f, o1 = 0.f;
    const int qmax = blockIdx.x * 8 + 7;
    const int ntiles = (qmax >> 6) + 1;

    for (int t0 = 0; t0 < ntiles; t0++) {
        int j0 = t0 * 64;
        __syncthreads();
        #pragma unroll
        for (int i = 0; i < 4; i++) {
            int f = threadIdx.x + 256 * i;     // 0..1023 float4 slots
            int r = f >> 4, c = (f & 15) * 4;
            *(float4*)&Ks[r][c] = *(const float4*)(kb + (size_t)(j0 + r) * HD_ + c);
            *(float4*)&Vs[r][c] = *(const float4*)(vb + (size_t)(j0 + r) * HD_ + c);
        }
        __syncthreads();

        #pragma unroll
        for (int hh = 0; hh < 2; hh++) {
            int jbase = j0 + hh * 32;
            if (jbase > qi) break;
            int j = jbase + lane;
            // score for key j (one key per lane)
            float s = 0.f;
            const float* kr = &Ks[hh * 32 + lane][0];
            const float* qr = &qs[warp][0];
            #pragma unroll
            for (int d = 0; d < 64; d += 4) {
                float4 kv = *(const float4*)(kr + d);
                float4 qv = *(const float4*)(qr + d);
                s += qv.x * kv.x + qv.y * kv.y + qv.z * kv.z + qv.w * kv.w;
            }
            s *= 0.125f;
            if (j > qi) s = -1e30f;

            float mt = s;
            #pragma unroll
            for (int off = 16; off; off >>= 1)
                mt = fmaxf(mt, __shfl_xor_sync(0xffffffffu, mt, off));
            float mn   = fmaxf(mx, mt);
            float corr = __expf(mx - mn);
            float e    = __expf(s - mn);
            float es   = e;
            #pragma unroll
            for (int off = 16; off; off >>= 1)
                es += __shfl_xor_sync(0xffffffffu, es, off);
            l  = l * corr + es;
            o0 *= corr; o1 *= corr;
            mx = mn;

            #pragma unroll
            for (int jj = 0; jj < 32; jj++) {
                float ej = __shfl_sync(0xffffffffu, e, jj);
                o0 += ej * Vs[hh * 32 + jj][lane];
                o1 += ej * Vs[hh * 32 + jj][lane + 32];
            }
        }
    }

    float invl = 1.0f / l;
    float* op = o + ((size_t)(b * T_ + qi)) * D_ + h * HD_;
    op[lane]      = o0 * invl;
    op[lane + 32] = o1 * invl;
}

// ---------------- head GEMV --------------------------------------------------
__global__ __launch_bounds__(256)
void head_k(const float* __restrict__ hf, const float* __restrict__ W,
            const float* __restrict__ hb, float* __restrict__ out) {
    __shared__ float s0[D_];
    __shared__ float s1[D_];
    for (int i = threadIdx.x; i < D_; i += 256) { s0[i] = hf[i]; s1[i] = hf[D_ + i]; }
    __syncthreads();
    int vcol = blockIdx.x * 256 + threadIdx.x;
    float a0 = 0.f, a1 = 0.f;
    #pragma unroll 4
    for (int d = 0; d < D_; d++) {
        float wv = W[(size_t)d * V_ + vcol];
        a0 += s0[d] * wv;
        a1 += s1[d] * wv;
    }
    float bb = hb[vcol];
    out[vcol]      = a0 + bb;
    out[V_ + vcol] = a1 + bb;
}

// ---------------- launch --------------------------------------------------
extern "C" void kernel_launch(void* const* d_in, const int* in_sizes, int n_in,
                              void* d_out, int out_size) {
    const int*   idx    = (const int*)  d_in[0];
    const float* tok    = (const float*)d_in[1];
    const float* pos    = (const float*)d_in[2];
    const float* ln1w   = (const float*)d_in[3];
    const float* ln1b   = (const float*)d_in[4];
    const float* qw     = (const float*)d_in[5];
    const float* qb     = (const float*)d_in[6];
    const float* kw     = (const float*)d_in[7];
    const float* kb     = (const float*)d_in[8];
    const float* vw     = (const float*)d_in[9];
    const float* vb     = (const float*)d_in[10];
    const float* ow     = (const float*)d_in[11];
    const float* ob     = (const float*)d_in[12];
    const float* ln2w   = (const float*)d_in[13];
    const float* ln2b   = (const float*)d_in[14];
    const float* f1w    = (const float*)d_in[15];
    const float* f1b    = (const float*)d_in[16];
    const float* f2w    = (const float*)d_in[17];
    const float* f2b    = (const float*)d_in[18];
    const float* lnfw   = (const float*)d_in[19];
    const float* lnfb   = (const float*)d_in[20];
    const float* headw  = (const float*)d_in[21];
    const float* headb  = (const float*)d_in[22];

    float *x, *h, *q, *k, *v, *o, *ff, *hf;
    cudaGetSymbolAddress((void**)&x,  g_x);
    cudaGetSymbolAddress((void**)&h,  g_h);
    cudaGetSymbolAddress((void**)&q,  g_q);
    cudaGetSymbolAddress((void**)&k,  g_k);
    cudaGetSymbolAddress((void**)&v,  g_v);
    cudaGetSymbolAddress((void**)&o,  g_o);
    cudaGetSymbolAddress((void**)&ff, g_ff);
    cudaGetSymbolAddress((void**)&hf, g_hf);

    embed_k<<<M_, 256>>>(idx, tok, pos);

    dim3 gDD(D_ / 128, M_ / 128);    // (8, 16)
    dim3 gDF(FF_ / 128, M_ / 128);   // (32, 16)
    dim3 gAt(T_ / 8, B_ * H_);       // (128, 32)

    for (int l = 0; l < L_; l++) {
        size_t wDD = (size_t)l * D_ * D_;
        size_t wDF = (size_t)l * D_ * FF_;

        ln_k<<<M_, 256>>>(x, D_, ln1w + l * D_, ln1b + l * D_, h, D_);

        gemm_k<false, true,  false><<<gDD, 256>>>(h, qw + wDD, qb + l * D_, nullptr, q, D_, D_);
        gemm_k<false, true,  false><<<gDD, 256>>>(h, kw + wDD, kb + l * D_, nullptr, k, D_, D_);
        gemm_k<false, true,  false><<<gDD, 256>>>(h, vw + wDD, vb + l * D_, nullptr, v, D_, D_);

        attn_k<<<gAt, 256>>>(q, k, v, o);

        gemm_k<false, false, true ><<<gDD, 256>>>(o, ow + wDD, ob + l * D_, x, x, D_, D_);

        ln_k<<<M_, 256>>>(x, D_, ln2w + l * D_, ln2b + l * D_, h, D_);

        gemm_k<true,  false, false><<<gDF, 256>>>(h,  f1w + wDF, f1b + l * FF_, nullptr, ff, FF_, D_);
        gemm_k<false, false, true ><<<gDD, 256>>>(ff, f2w + wDF, f2b + l * D_,  x,       x,  D_, FF_);
    }

    ln_k<<<B_, 256>>>(x + (size_t)(T_ - 1) * D_, (long)T_ * D_, lnfw, lnfb, hf, D_);

    head_k<<<V_ / 256, 256>>>(hf, headw, headb, (float*)d_out);
}

// round 4
// speedup vs baseline: 2.4506x; 1.5714x over previous
#include <cuda_runtime.h>
#include <cuda_bf16.h>
#include <cstdint>

#define D_  1024
#define H_  16
#define HD_ 64
#define T_  1024
#define B_  2
#define L_  8
#define FF_ 4096
#define V_  32000
#define M_  (B_ * T_)   // 2048 rows

// converted-weight layout (elements), per layer: Q,K,V,O (1M each), F1 (4M), F2 (4M)
#define WMEG     (1024 * 1024)
#define WL_Q     0
#define WL_O     (3 * WMEG)
#define WL_F1    (4 * WMEG)
#define WL_F2    (8 * WMEG)
#define WL_STRIDE (12 * WMEG)

// ---------------- scratch (device globals) ----------------------------------
__device__ __nv_bfloat16 g_whi[(size_t)L_ * WL_STRIDE];
__device__ __nv_bfloat16 g_wlo[(size_t)L_ * WL_STRIDE];
__device__ float g_x  [M_ * D_];
__device__ float g_qkv[3 * M_ * D_];
__device__ __nv_bfloat16 g_hhi [M_ * D_],  g_hlo [M_ * D_];
__device__ __nv_bfloat16 g_ohi [M_ * D_],  g_olo [M_ * D_];
__device__ __nv_bfloat16 g_ffhi[M_ * FF_], g_fflo[M_ * FF_];
__device__ float g_hf[B_ * D_];

// ---------------- ptx helpers ------------------------------------------------
__device__ __forceinline__ uint32_t smem_u32(const void* p) {
    uint32_t a;
    asm("{ .reg .u64 t; cvta.to.shared.u64 t, %1; cvt.u32.u64 %0, t; }" : "=r"(a) : "l"(p));
    return a;
}

#define LDSM4(r, a) \
    asm volatile("ldmatrix.sync.aligned.m8n8.x4.shared.b16 {%0,%1,%2,%3}, [%4];" \
        : "=r"((r)[0]), "=r"((r)[1]), "=r"((r)[2]), "=r"((r)[3]) : "r"(a))
#define LDSM2(r, a) \
    asm volatile("ldmatrix.sync.aligned.m8n8.x2.shared.b16 {%0,%1}, [%2];" \
        : "=r"((r)[0]), "=r"((r)[1]) : "r"(a))
#define MMA_BF16(c, a, b) \
    asm volatile("mma.sync.aligned.m16n8k16.row.col.f32.bf16.bf16.f32 " \
        "{%0,%1,%2,%3}, {%4,%5,%6,%7}, {%8,%9}, {%0,%1,%2,%3};" \
        : "+f"((c)[0]), "+f"((c)[1]), "+f"((c)[2]), "+f"((c)[3]) \
        : "r"((a)[0]), "r"((a)[1]), "r"((a)[2]), "r"((a)[3]), "r"((b)[0]), "r"((b)[1]))
#define CP_ASYNC16(d, g) \
    asm volatile("cp.async.cg.shared.global [%0], [%1], 16;" :: "r"(d), "l"(g))
#define CP_COMMIT() asm volatile("cp.async.commit_group;" ::: "memory")
#define CP_WAIT0()  asm volatile("cp.async.wait_group 0;" ::: "memory")

// ---------------- embedding ---------------------------------------------------
__global__ void embed_k(const int* __restrict__ idx,
                        const float* __restrict__ tok,
                        const float* __restrict__ pos) {
    int m = blockIdx.x;
    int t = m & (T_ - 1);
    const float* te = tok + (size_t)idx[m] * D_;
    const float* pe = pos + (size_t)t * D_;
    float* xr = g_x + (size_t)m * D_;
    for (int d = threadIdx.x; d < D_; d += blockDim.x)
        xr[d] = te[d] + pe[d];
}

// ---------------- weight convert + transpose: W[K,N] fp32 -> [N,K] bf16 pair --
__global__ void convw_k(const float* __restrict__ W, int K, int N,
                        __nv_bfloat16* __restrict__ hi, __nv_bfloat16* __restrict__ lo) {
    __shared__ float ts[32][33];
    int n0 = blockIdx.x * 32, k0 = blockIdx.y * 32;
    int tx = threadIdx.x, ty = threadIdx.y;   // 32 x 8
    #pragma unroll
    for (int i = 0; i < 4; i++)
        ts[ty + 8 * i][tx] = W[(size_t)(k0 + ty + 8 * i) * N + n0 + tx];
    __syncthreads();
    #pragma unroll
    for (int i = 0; i < 4; i++) {
        float v = ts[tx][ty + 8 * i];
        size_t o = (size_t)(n0 + ty + 8 * i) * K + k0 + tx;
        __nv_bfloat16 h = __float2bfloat16_rn(v);
        hi[o] = h;
        lo[o] = __float2bfloat16_rn(v - __bfloat162float(h));
    }
}

// ---------------- layernorm: writes bf16 pair (and/or fp32) -------------------
__global__ void ln_k(const float* __restrict__ in, long in_stride,
                     const float* __restrict__ w, const float* __restrict__ b,
                     __nv_bfloat16* __restrict__ ohi, __nv_bfloat16* __restrict__ olo,
                     float* __restrict__ of) {
    const float* row = in + (size_t)blockIdx.x * in_stride;
    int tid = threadIdx.x;
    float vals[4];
    float s = 0.f;
    #pragma unroll
    for (int i = 0; i < 4; i++) { vals[i] = row[tid + 256 * i]; s += vals[i]; }

    __shared__ float red[8];
    int lane = tid & 31, warp = tid >> 5;
    #pragma unroll
    for (int off = 16; off; off >>= 1) s += __shfl_xor_sync(0xffffffffu, s, off);
    if (lane == 0) red[warp] = s;
    __syncthreads();
    float tot = 0.f;
    #pragma unroll
    for (int i = 0; i < 8; i++) tot += red[i];
    float mean = tot * (1.0f / D_);

    float s2 = 0.f;
    #pragma unroll
    for (int i = 0; i < 4; i++) { float d = vals[i] - mean; s2 += d * d; }
    __syncthreads();
    #pragma unroll
    for (int off = 16; off; off >>= 1) s2 += __shfl_xor_sync(0xffffffffu, s2, off);
    if (lane == 0) red[warp] = s2;
    __syncthreads();
    float tot2 = 0.f;
    #pragma unroll
    for (int i = 0; i < 8; i++) tot2 += red[i];
    float inv = rsqrtf(tot2 * (1.0f / D_) + 1e-5f);

    size_t base = (size_t)blockIdx.x * D_;
    #pragma unroll
    for (int i = 0; i < 4; i++) {
        int d = tid + 256 * i;
        float v = (vals[i] - mean) * inv * w[d] + b[d];
        if (of) of[base + d] = v;
        if (ohi) {
            __nv_bfloat16 h = __float2bfloat16_rn(v);
            ohi[base + d] = h;
            olo[base + d] = __float2bfloat16_rn(v - __bfloat162float(h));
        }
    }
}

// ---------------- mma.sync bf16 GEMM with hi/lo split, 128x128x32 pipeline ----
// A: [M,K] K-major bf16 pair. B: [N,K] K-major bf16 pair (pre-transposed).
// MODE 0: QKV fp32 out, permute to [3][B,H,T,HD], bias from 3 ptrs
// MODE 1: fp32 out = acc + bias0 + res
// MODE 2: bf16-pair out = relu(acc + bias0)
// smem: 2 stages x 4 tiles x [128 rows x 32 bf16 cols, 80B row stride] = 81920 B
#define TILE_B   10240              // bytes per tile (128 * 80)
#define STAGE_B  (4 * TILE_B)       // 40960
#define GSMEM    (2 * STAGE_B)      // 81920

template<int MODE>
__global__ __launch_bounds__(256, 1)
void gemm_tc(const __nv_bfloat16* __restrict__ Ahi, const __nv_bfloat16* __restrict__ Alo,
             const __nv_bfloat16* __restrict__ Bhi, const __nv_bfloat16* __restrict__ Blo,
             const float* __restrict__ bias0, const float* __restrict__ bias1,
             const float* __restrict__ bias2, const float* __restrict__ res,
             float* __restrict__ Cf,
             __nv_bfloat16* __restrict__ Chi, __nv_bfloat16* __restrict__ Clo,
             int Kdim, int Nout) {
    extern __shared__ char smem[];
    const uint32_t sb = smem_u32(smem);
    const int tid = threadIdx.x, lane = tid & 31, wid = tid >> 5;
    const int bm = blockIdx.y * 128, bn = blockIdx.x * 128;
    const int wm = wid & 1, wn = wid >> 1;     // warp tile: 64 x 32

    const __nv_bfloat16* srcs[4] = {
        Ahi + (size_t)bm * Kdim, Alo + (size_t)bm * Kdim,
        Bhi + (size_t)bn * Kdim, Blo + (size_t)bn * Kdim };

    const int lr = tid >> 2;       // 0..63
    const int lc = tid & 3;        // 16B chunk within 64B row

    const int KT = Kdim >> 5;      // K tiles of 32

    // prologue: stage 0
    #pragma unroll
    for (int t = 0; t < 4; t++) {
        #pragma unroll
        for (int i = 0; i < 2; i++) {
            int r = i * 64 + lr;
            const void* g = srcs[t] + (size_t)r * Kdim + lc * 8;
            uint32_t d = sb + t * TILE_B + r * 80 + lc * 16;
            CP_ASYNC16(d, g);
        }
    }
    CP_COMMIT();

    float acc[4][4][4] = {};

    for (int s = 0; s < KT; s++) {
        CP_WAIT0();
        __syncthreads();
        if (s + 1 < KT) {
            const int buf = (s + 1) & 1;
            #pragma unroll
            for (int t = 0; t < 4; t++) {
                #pragma unroll
                for (int i = 0; i < 2; i++) {
                    int r = i * 64 + lr;
                    const void* g = srcs[t] + (size_t)r * Kdim + (s + 1) * 32 + lc * 8;
                    uint32_t d = sb + buf * STAGE_B + t * TILE_B + r * 80 + lc * 16;
                    CP_ASYNC16(d, g);
                }
            }
            CP_COMMIT();
        }

        const uint32_t base = sb + (s & 1) * STAGE_B;
        #pragma unroll
        for (int ks = 0; ks < 2; ks++) {
            const int kb = ks * 32;   // byte offset of k-step
            uint32_t ah[4][4], al[4][4], bh[4][2], bl[4][2];
            #pragma unroll
            for (int mi = 0; mi < 4; mi++) {
                uint32_t ra = base + (wm * 64 + mi * 16 + (lane & 15)) * 80 + kb + (lane >> 4) * 16;
                LDSM4(ah[mi], ra);
                LDSM4(al[mi], ra + TILE_B);
            }
            #pragma unroll
            for (int ni = 0; ni < 4; ni++) {
                uint32_t rb = base + 2 * TILE_B + (wn * 32 + ni * 8 + (lane & 7)) * 80 + kb + ((lane >> 3) & 1) * 16;
                LDSM2(bh[ni], rb);
                LDSM2(bl[ni], rb + TILE_B);
            }
            #pragma unroll
            for (int mi = 0; mi < 4; mi++)
                #pragma unroll
                for (int ni = 0; ni < 4; ni++) {
                    MMA_BF16(acc[mi][ni], ah[mi], bh[ni]);
                    MMA_BF16(acc[mi][ni], ah[mi], bl[ni]);
                    MMA_BF16(acc[mi][ni], al[mi], bh[ni]);
                }
        }
    }

    // epilogue: per thread, rows r0/r0+8, col pairs
    #pragma unroll
    for (int mi = 0; mi < 4; mi++) {
        const int r0 = bm + wm * 64 + mi * 16 + (lane >> 2);
        #pragma unroll
        for (int rr = 0; rr < 2; rr++) {
            const int m = r0 + rr * 8;
            const int bt = m >> 10, tt = m & (T_ - 1);
            #pragma unroll
            for (int ni = 0; ni < 4; ni++) {
                const int cc = bn + wn * 32 + ni * 8 + (lane & 3) * 2;
                float v0 = acc[mi][ni][rr * 2 + 0];
                float v1 = acc[mi][ni][rr * 2 + 1];
                if (MODE == 0) {
                    const int which = cc >> 10;
                    const int nn = cc & 1023;
                    const float* bp = (which == 0) ? bias0 : (which == 1 ? bias1 : bias2);
                    const int h = nn >> 6, hd = nn & 63;
                    float* dst = Cf + (size_t)which * (M_ * D_) +
                                 ((size_t)(bt * H_ + h) * T_ + tt) * HD_ + hd;
                    float2 bv = *(const float2*)(bp + nn);
                    float2 o2 = {v0 + bv.x, v1 + bv.y};
                    *(float2*)dst = o2;
                } else if (MODE == 1) {
                    size_t idx = (size_t)m * Nout + cc;
                    float2 bv = *(const float2*)(bias0 + cc);
                    float2 rv = *(const float2*)(res + idx);
                    float2 o2 = {v0 + bv.x + rv.x, v1 + bv.y + rv.y};
                    *(float2*)(Cf + idx) = o2;
                } else {
                    size_t idx = (size_t)m * Nout + cc;
                    float2 bv = *(const float2*)(bias0 + cc);
                    float a0 = fmaxf(v0 + bv.x, 0.f);
                    float a1 = fmaxf(v1 + bv.y, 0.f);
                    __nv_bfloat16 h0 = __float2bfloat16_rn(a0);
                    __nv_bfloat16 h1 = __float2bfloat16_rn(a1);
                    __nv_bfloat162 hh; hh.x = h0; hh.y = h1;
                    __nv_bfloat162 ll;
                    ll.x = __float2bfloat16_rn(a0 - __bfloat162float(h0));
                    ll.y = __float2bfloat16_rn(a1 - __bfloat162float(h1));
                    *(__nv_bfloat162*)(Chi + idx) = hh;
                    *(__nv_bfloat162*)(Clo + idx) = ll;
                }
            }
        }
    }
}

// ---------------- flash attention (fp32), writes bf16 pair -------------------
__global__ __launch_bounds__(256)
void attn_k(const float* __restrict__ q, const float* __restrict__ k,
            const float* __restrict__ v,
            __nv_bfloat16* __restrict__ ohi, __nv_bfloat16* __restrict__ olo) {
    __shared__ float Ks[64][68];
    __shared__ float Vs[64][68];
    __shared__ float qs[8][64];

    int bh   = blockIdx.y;
    int warp = threadIdx.x >> 5;
    int lane = threadIdx.x & 31;
    int qi   = blockIdx.x * 8 + warp;
    int b = bh >> 4, h = bh & 15;

    const float* kb = k + (size_t)bh * T_ * HD_;
    const float* vb = v + (size_t)bh * T_ * HD_;
    const float* qp = q + ((size_t)bh * T_ + qi) * HD_;
    qs[warp][lane]      = qp[lane];
    qs[warp][lane + 32] = qp[lane + 32];

    float mx = -1e30f, l = 0.f, o0 = 0.f, o1 = 0.f;
    const int qmax = blockIdx.x * 8 + 7;
    const int ntiles = (qmax >> 6) + 1;

    for (int t0 = 0; t0 < ntiles; t0++) {
        int j0 = t0 * 64;
        __syncthreads();
        #pragma unroll
        for (int i = 0; i < 4; i++) {
            int f = threadIdx.x + 256 * i;
            int r = f >> 4, c = (f & 15) * 4;
            *(float4*)&Ks[r][c] = *(const float4*)(kb + (size_t)(j0 + r) * HD_ + c);
            *(float4*)&Vs[r][c] = *(const float4*)(vb + (size_t)(j0 + r) * HD_ + c);
        }
        __syncthreads();

        #pragma unroll
        for (int hh = 0; hh < 2; hh++) {
            int jbase = j0 + hh * 32;
            if (jbase > qi) break;
            int j = jbase + lane;
            float s = 0.f;
            const float* kr = &Ks[hh * 32 + lane][0];
            const float* qr = &qs[warp][0];
            #pragma unroll
            for (int d = 0; d < 64; d += 4) {
                float4 kv = *(const float4*)(kr + d);
                float4 qv = *(const float4*)(qr + d);
                s += qv.x * kv.x + qv.y * kv.y + qv.z * kv.z + qv.w * kv.w;
            }
            s *= 0.125f;
            if (j > qi) s = -1e30f;

            float mt = s;
            #pragma unroll
            for (int off = 16; off; off >>= 1)
                mt = fmaxf(mt, __shfl_xor_sync(0xffffffffu, mt, off));
            float mn   = fmaxf(mx, mt);
            float corr = __expf(mx - mn);
            float e    = __expf(s - mn);
            float es   = e;
            #pragma unroll
            for (int off = 16; off; off >>= 1)
                es += __shfl_xor_sync(0xffffffffu, es, off);
            l  = l * corr + es;
            o0 *= corr; o1 *= corr;
            mx = mn;

            #pragma unroll
            for (int jj = 0; jj < 32; jj++) {
                float ej = __shfl_sync(0xffffffffu, e, jj);
                o0 += ej * Vs[hh * 32 + jj][lane];
                o1 += ej * Vs[hh * 32 + jj][lane + 32];
            }
        }
    }

    float invl = 1.0f / l;
    float v0 = o0 * invl, v1 = o1 * invl;
    size_t base = ((size_t)(b * T_ + qi)) * D_ + h * HD_;
    __nv_bfloat16 h0 = __float2bfloat16_rn(v0);
    __nv_bfloat16 h1 = __float2bfloat16_rn(v1);
    ohi[base + lane]      = h0;
    ohi[base + lane + 32] = h1;
    olo[base + lane]      = __float2bfloat16_rn(v0 - __bfloat162float(h0));
    olo[base + lane + 32] = __float2bfloat16_rn(v1 - __bfloat162float(h1));
}

// ---------------- head GEMV ----------------------------------------------------
__global__ __launch_bounds__(256)
void head_k(const float* __restrict__ hf, const float* __restrict__ W,
            const float* __restrict__ hb, float* __restrict__ out) {
    __shared__ float s0[D_];
    __shared__ float s1[D_];
    for (int i = threadIdx.x; i < D_; i += 256) { s0[i] = hf[i]; s1[i] = hf[D_ + i]; }
    __syncthreads();
    int vcol = blockIdx.x * 256 + threadIdx.x;
    float a0 = 0.f, a1 = 0.f;
    #pragma unroll 4
    for (int d = 0; d < D_; d++) {
        float wv = W[(size_t)d * V_ + vcol];
        a0 += s0[d] * wv;
        a1 += s1[d] * wv;
    }
    float bb = hb[vcol];
    out[vcol]      = a0 + bb;
    out[V_ + vcol] = a1 + bb;
}

// ---------------- launch --------------------------------------------------
extern "C" void kernel_launch(void* const* d_in, const int* in_sizes, int n_in,
                              void* d_out, int out_size) {
    const int*   idx    = (const int*)  d_in[0];
    const float* tok    = (const float*)d_in[1];
    const float* pos    = (const float*)d_in[2];
    const float* ln1w   = (const float*)d_in[3];
    const float* ln1b   = (const float*)d_in[4];
    const float* qw     = (const float*)d_in[5];
    const float* qb     = (const float*)d_in[6];
    const float* kw     = (const float*)d_in[7];
    const float* kbi    = (const float*)d_in[8];
    const float* vw     = (const float*)d_in[9];
    const float* vb     = (const float*)d_in[10];
    const float* ow     = (const float*)d_in[11];
    const float* ob     = (const float*)d_in[12];
    const float* ln2w   = (const float*)d_in[13];
    const float* ln2b   = (const float*)d_in[14];
    const float* f1w    = (const float*)d_in[15];
    const float* f1b    = (const float*)d_in[16];
    const float* f2w    = (const float*)d_in[17];
    const float* f2b    = (const float*)d_in[18];
    const float* lnfw   = (const float*)d_in[19];
    const float* lnfb   = (const float*)d_in[20];
    const float* headw  = (const float*)d_in[21];
    const float* headb  = (const float*)d_in[22];

    float *x, *qkv, *hf;
    __nv_bfloat16 *whi, *wlo, *hhi, *hlo, *ohi, *olo, *ffhi, *fflo;
    cudaGetSymbolAddress((void**)&x,    g_x);
    cudaGetSymbolAddress((void**)&qkv,  g_qkv);
    cudaGetSymbolAddress((void**)&hf,   g_hf);
    cudaGetSymbolAddress((void**)&whi,  g_whi);
    cudaGetSymbolAddress((void**)&wlo,  g_wlo);
    cudaGetSymbolAddress((void**)&hhi,  g_hhi);
    cudaGetSymbolAddress((void**)&hlo,  g_hlo);
    cudaGetSymbolAddress((void**)&ohi,  g_ohi);
    cudaGetSymbolAddress((void**)&olo,  g_olo);
    cudaGetSymbolAddress((void**)&ffhi, g_ffhi);
    cudaGetSymbolAddress((void**)&fflo, g_fflo);

    cudaFuncSetAttribute(gemm_tc<0>, cudaFuncAttributeMaxDynamicSharedMemorySize, GSMEM);
    cudaFuncSetAttribute(gemm_tc<1>, cudaFuncAttributeMaxDynamicSharedMemorySize, GSMEM);
    cudaFuncSetAttribute(gemm_tc<2>, cudaFuncAttributeMaxDynamicSharedMemorySize, GSMEM);

    // ---- weight conversion (transpose to [N,K] bf16 hi/lo) ----
    dim3 cb(32, 8);
    for (int l = 0; l < L_; l++) {
        size_t wb = (size_t)l * WL_STRIDE;
        convw_k<<<dim3(32, 32), cb>>>(qw + (size_t)l * D_ * D_,  D_,  D_,  whi + wb + WL_Q,           wlo + wb + WL_Q);
        convw_k<<<dim3(32, 32), cb>>>(kw + (size_t)l * D_ * D_,  D_,  D_,  whi + wb + WL_Q + WMEG,    wlo + wb + WL_Q + WMEG);
        convw_k<<<dim3(32, 32), cb>>>(vw + (size_t)l * D_ * D_,  D_,  D_,  whi + wb + WL_Q + 2*WMEG,  wlo + wb + WL_Q + 2*WMEG);
        convw_k<<<dim3(32, 32), cb>>>(ow + (size_t)l * D_ * D_,  D_,  D_,  whi + wb + WL_O,           wlo + wb + WL_O);
        convw_k<<<dim3(128, 32), cb>>>(f1w + (size_t)l * D_ * FF_, D_,  FF_, whi + wb + WL_F1,        wlo + wb + WL_F1);
        convw_k<<<dim3(32, 128), cb>>>(f2w + (size_t)l * FF_ * D_, FF_, D_,  whi + wb + WL_F2,        wlo + wb + WL_F2);
    }

    embed_k<<<M_, 256>>>(idx, tok, pos);

    dim3 gQKV(24, 16), gDD(8, 16), gF1(32, 16);
    dim3 gAt(T_ / 8, B_ * H_);

    for (int l = 0; l < L_; l++) {
        size_t wb = (size_t)l * WL_STRIDE;

        ln_k<<<M_, 256>>>(x, D_, ln1w + l * D_, ln1b + l * D_, hhi, hlo, nullptr);

        gemm_tc<0><<<gQKV, 256, GSMEM>>>(hhi, hlo, whi + wb + WL_Q, wlo + wb + WL_Q,
                                         qb + l * D_, kbi + l * D_, vb + l * D_,
                                         nullptr, qkv, nullptr, nullptr, D_, 0);

        attn_k<<<gAt, 256>>>(qkv, qkv + M_ * D_, qkv + 2 * M_ * D_, ohi, olo);

        gemm_tc<1><<<gDD, 256, GSMEM>>>(ohi, olo, whi + wb + WL_O, wlo + wb + WL_O,
                                        ob + l * D_, nullptr, nullptr,
                                        x, x, nullptr, nullptr, D_, D_);

        ln_k<<<M_, 256>>>(x, D_, ln2w + l * D_, ln2b + l * D_, hhi, hlo, nullptr);

        gemm_tc<2><<<gF1, 256, GSMEM>>>(hhi, hlo, whi + wb + WL_F1, wlo + wb + WL_F1,
                                        f1b + l * FF_, nullptr, nullptr,
                                        nullptr, nullptr, ffhi, fflo, D_, FF_);

        gemm_tc<1><<<gDD, 256, GSMEM>>>(ffhi, fflo, whi + wb + WL_F2, wlo + wb + WL_F2,
                                        f2b + l * D_, nullptr, nullptr,
                                        x, x, nullptr, nullptr, FF_, D_);
    }

    ln_k<<<B_, 256>>>(x + (size_t)(T_ - 1) * D_, (long)T_ * D_, lnfw, lnfb,
                      nullptr, nullptr, hf);

    head_k<<<V_ / 256, 256>>>(hf, headw, headb, (float*)d_out);
}

// round 5
// speedup vs baseline: 2.5754x; 1.0509x over previous
#include <cuda_runtime.h>
#include <cuda_bf16.h>
#include <cstdint>

#define D_  1024
#define H_  16
#define HD_ 64
#define T_  1024
#define B_  2
#define L_  8
#define FF_ 4096
#define V_  32000
#define M_  (B_ * T_)   // 2048 rows

// ---------------- scratch (device globals) ----------------------------------
// converted weights, K-major [K][N] bf16 hi/lo
__device__ __nv_bfloat16 g_wqkv_h[(size_t)L_ * D_ * 3 * D_], g_wqkv_l[(size_t)L_ * D_ * 3 * D_];
__device__ __nv_bfloat16 g_wo_h  [(size_t)L_ * D_ * D_],     g_wo_l  [(size_t)L_ * D_ * D_];
__device__ __nv_bfloat16 g_wf1_h [(size_t)L_ * D_ * FF_],    g_wf1_l [(size_t)L_ * D_ * FF_];
__device__ __nv_bfloat16 g_wf2_h [(size_t)L_ * FF_ * D_],    g_wf2_l [(size_t)L_ * FF_ * D_];
__device__ float g_x  [M_ * D_];
__device__ float g_qkv[3 * M_ * D_];
__device__ __nv_bfloat16 g_hhi [M_ * D_],  g_hlo [M_ * D_];
__device__ __nv_bfloat16 g_ohi [M_ * D_],  g_olo [M_ * D_];
__device__ __nv_bfloat16 g_ffhi[M_ * FF_], g_fflo[M_ * FF_];
__device__ float g_hf[B_ * D_];

// ---------------- ptx helpers ------------------------------------------------
__device__ __forceinline__ uint32_t smem_u32(const void* p) {
    uint32_t a;
    asm("{ .reg .u64 t; cvta.to.shared.u64 t, %1; cvt.u32.u64 %0, t; }" : "=r"(a) : "l"(p));
    return a;
}

#define LDSM4(r, a) \
    asm volatile("ldmatrix.sync.aligned.m8n8.x4.shared.b16 {%0,%1,%2,%3}, [%4];" \
        : "=r"((r)[0]), "=r"((r)[1]), "=r"((r)[2]), "=r"((r)[3]) : "r"(a))
#define LDSM4T(r, a) \
    asm volatile("ldmatrix.sync.aligned.m8n8.x4.trans.shared.b16 {%0,%1,%2,%3}, [%4];" \
        : "=r"((r)[0]), "=r"((r)[1]), "=r"((r)[2]), "=r"((r)[3]) : "r"(a))
#define MMA_BF16(c, a, b) \
    asm volatile("mma.sync.aligned.m16n8k16.row.col.f32.bf16.bf16.f32 " \
        "{%0,%1,%2,%3}, {%4,%5,%6,%7}, {%8,%9}, {%0,%1,%2,%3};" \
        : "+f"((c)[0]), "+f"((c)[1]), "+f"((c)[2]), "+f"((c)[3]) \
        : "r"((a)[0]), "r"((a)[1]), "r"((a)[2]), "r"((a)[3]), "r"((b)[0]), "r"((b)[1]))
#define CP_ASYNC16(d, g) \
    asm volatile("cp.async.cg.shared.global [%0], [%1], 16;" :: "r"(d), "l"(g))
#define CP_COMMIT() asm volatile("cp.async.commit_group;" ::: "memory")
#define CP_WAIT0()  asm volatile("cp.async.wait_group 0;" ::: "memory")
#define CP_WAIT1()  asm volatile("cp.async.wait_group 1;" ::: "memory")

// ---------------- embedding ---------------------------------------------------
__global__ void embed_k(const int* __restrict__ idx,
                        const float* __restrict__ tok,
                        const float* __restrict__ pos) {
    int m = blockIdx.x;
    int t = m & (T_ - 1);
    const float* te = tok + (size_t)idx[m] * D_;
    const float* pe = pos + (size_t)t * D_;
    float* xr = g_x + (size_t)m * D_;
    for (int d = threadIdx.x; d < D_; d += blockDim.x)
        xr[d] = te[d] + pe[d];
}

// ---------------- weight convert (elementwise, no transpose) ------------------
// W [K][Nsrc] fp32 -> hi/lo bf16 at [K][Ndst] with column offset. z = layer.
__global__ void convw2(const float* __restrict__ W,
                       __nv_bfloat16* __restrict__ hi, __nv_bfloat16* __restrict__ lo,
                       int nshift, int nmask, int Ndst, int colOff,
                       long srcL, long dstL) {
    long z = blockIdx.y;
    long i4 = (long)blockIdx.x * 256 + threadIdx.x;
    long idx = i4 * 4;
    int k = (int)(idx >> nshift);
    int n = (int)(idx & nmask);
    float4 v = *(const float4*)(W + z * srcL + idx);
    size_t d = (size_t)z * dstL + (size_t)k * Ndst + colOff + n;
    union { uint2 u; __nv_bfloat16 b[4]; } ph, pl;
    float vv[4] = {v.x, v.y, v.z, v.w};
    #pragma unroll
    for (int i = 0; i < 4; i++) {
        __nv_bfloat16 h = __float2bfloat16_rn(vv[i]);
        ph.b[i] = h;
        pl.b[i] = __float2bfloat16_rn(vv[i] - __bfloat162float(h));
    }
    *(uint2*)(hi + d) = ph.u;
    *(uint2*)(lo + d) = pl.u;
}

// ---------------- layernorm: writes bf16 pair (and/or fp32) -------------------
__global__ void ln_k(const float* __restrict__ in, long in_stride,
                     const float* __restrict__ w, const float* __restrict__ b,
                     __nv_bfloat16* __restrict__ ohi, __nv_bfloat16* __restrict__ olo,
                     float* __restrict__ of) {
    const float* row = in + (size_t)blockIdx.x * in_stride;
    int tid = threadIdx.x;
    float vals[4];
    float s = 0.f;
    #pragma unroll
    for (int i = 0; i < 4; i++) { vals[i] = row[tid + 256 * i]; s += vals[i]; }

    __shared__ float red[8];
    int lane = tid & 31, warp = tid >> 5;
    #pragma unroll
    for (int off = 16; off; off >>= 1) s += __shfl_xor_sync(0xffffffffu, s, off);
    if (lane == 0) red[warp] = s;
    __syncthreads();
    float tot = 0.f;
    #pragma unroll
    for (int i = 0; i < 8; i++) tot += red[i];
    float mean = tot * (1.0f / D_);

    float s2 = 0.f;
    #pragma unroll
    for (int i = 0; i < 4; i++) { float d = vals[i] - mean; s2 += d * d; }
    __syncthreads();
    #pragma unroll
    for (int off = 16; off; off >>= 1) s2 += __shfl_xor_sync(0xffffffffu, s2, off);
    if (lane == 0) red[warp] = s2;
    __syncthreads();
    float tot2 = 0.f;
    #pragma unroll
    for (int i = 0; i < 8; i++) tot2 += red[i];
    float inv = rsqrtf(tot2 * (1.0f / D_) + 1e-5f);

    size_t base = (size_t)blockIdx.x * D_;
    #pragma unroll
    for (int i = 0; i < 4; i++) {
        int d = tid + 256 * i;
        float v = (vals[i] - mean) * inv * w[d] + b[d];
        if (of) of[base + d] = v;
        if (ohi) {
            __nv_bfloat16 h = __float2bfloat16_rn(v);
            ohi[base + d] = h;
            olo[base + d] = __float2bfloat16_rn(v - __bfloat162float(h));
        }
    }
}

// ---------------- mma.sync bf16 GEMM, hi/lo split, 128x128x32, 3-stage --------
// A: [M,K] row-major bf16 pair. B: [K,N] row-major bf16 pair (K-major weights).
// MODE 0: QKV fp32 out, permute to [3][B,H,T,HD], bias from 3 ptrs
// MODE 1: fp32 out = acc + bias0 + res
// MODE 2: bf16-pair out = relu(acc + bias0)
// stage smem: Ahi(10240) Alo(10240) Bhi(8704) Blo(8704) = 37888; x3 = 113664
#define A_TILE   10240
#define B_TILE   8704
#define B_OFF    (2 * A_TILE)
#define STAGE_B  (2 * A_TILE + 2 * B_TILE)
#define GSMEM    (3 * STAGE_B)

template<int MODE>
__global__ __launch_bounds__(256, 1)
void gemm_tc(const __nv_bfloat16* __restrict__ Ahi, const __nv_bfloat16* __restrict__ Alo,
             const __nv_bfloat16* __restrict__ Bhi, const __nv_bfloat16* __restrict__ Blo,
             const float* __restrict__ bias0, const float* __restrict__ bias1,
             const float* __restrict__ bias2, const float* __restrict__ res,
             float* __restrict__ Cf,
             __nv_bfloat16* __restrict__ Chi, __nv_bfloat16* __restrict__ Clo,
             int Kdim, int Nb, int Nout) {
    extern __shared__ char smem[];
    const uint32_t sb = smem_u32(smem);
    const int tid = threadIdx.x, lane = tid & 31, wid = tid >> 5;
    const int bm = blockIdx.y * 128, bn = blockIdx.x * 128;
    const int wm = wid & 1, wn = wid >> 1;     // warp tile: 64 x 32

    const int KT = Kdim >> 5;

    auto load_stage = [&](int ss) {
        const uint32_t dst = sb + (ss % 3) * STAGE_B;
        const int kg = ss * 32;
        // A tiles: 128 rows x 64B (+2 for lo)
        #pragma unroll
        for (int i = 0; i < 2; i++) {
            int ch = tid + 256 * i;            // 0..511
            int r = ch >> 2, c = (ch & 3) * 8; // 8 bf16 = 16B
            const __nv_bfloat16* ga = Ahi + (size_t)(bm + r) * Kdim + kg + c;
            const __nv_bfloat16* gl = Alo + (size_t)(bm + r) * Kdim + kg + c;
            uint32_t da = dst + r * 80 + (ch & 3) * 16;
            CP_ASYNC16(da, ga);
            CP_ASYNC16(da + A_TILE, gl);
        }
        // B tiles: 32 rows x 256B (+pad 16)
        #pragma unroll
        for (int i = 0; i < 2; i++) {
            int ch = tid + 256 * i;             // 0..511
            int r = ch >> 4, c = (ch & 15) * 8; // 8 bf16 = 16B
            const __nv_bfloat16* gb = Bhi + (size_t)(kg + r) * Nb + bn + c;
            const __nv_bfloat16* gl = Blo + (size_t)(kg + r) * Nb + bn + c;
            uint32_t db = dst + B_OFF + r * 272 + (ch & 15) * 16;
            CP_ASYNC16(db, gb);
            CP_ASYNC16(db + B_TILE, gl);
        }
    };

    load_stage(0); CP_COMMIT();
    load_stage(1); CP_COMMIT();

    float acc[4][4][4] = {};

    for (int s = 0; s < KT; s++) {
        if (s == KT - 1) { CP_WAIT0(); } else { CP_WAIT1(); }
        __syncthreads();
        if (s + 2 < KT) { load_stage(s + 2); CP_COMMIT(); }

        const uint32_t base = sb + (s % 3) * STAGE_B;
        #pragma unroll
        for (int ks = 0; ks < 2; ks++) {
            uint32_t ah[4][4], al[4][4], bh[2][4], bl[2][4];
            #pragma unroll
            for (int mi = 0; mi < 4; mi++) {
                uint32_t ra = base + (wm * 64 + mi * 16 + (lane & 15)) * 80
                            + ks * 32 + (lane >> 4) * 16;
                LDSM4(ah[mi], ra);
                LDSM4(al[mi], ra + A_TILE);
            }
            #pragma unroll
            for (int g = 0; g < 2; g++) {
                uint32_t rb = base + B_OFF + (ks * 16 + (lane & 15)) * 272
                            + (wn * 32 + g * 16) * 2 + (lane >> 4) * 16;
                LDSM4T(bh[g], rb);
                LDSM4T(bl[g], rb + B_TILE);
            }
            #pragma unroll
            for (int mi = 0; mi < 4; mi++)
                #pragma unroll
                for (int ni = 0; ni < 4; ni++) {
                    const uint32_t* bhp = &bh[ni >> 1][(ni & 1) * 2];
                    const uint32_t* blp = &bl[ni >> 1][(ni & 1) * 2];
                    MMA_BF16(acc[mi][ni], ah[mi], bhp);
                    MMA_BF16(acc[mi][ni], ah[mi], blp);
                    MMA_BF16(acc[mi][ni], al[mi], bhp);
                }
        }
        __syncthreads();
    }

    // epilogue
    #pragma unroll
    for (int mi = 0; mi < 4; mi++) {
        const int r0 = bm + wm * 64 + mi * 16 + (lane >> 2);
        #pragma unroll
        for (int rr = 0; rr < 2; rr++) {
            const int m = r0 + rr * 8;
            const int bt = m >> 10, tt = m & (T_ - 1);
            #pragma unroll
            for (int ni = 0; ni < 4; ni++) {
                const int cc = bn + wn * 32 + ni * 8 + (lane & 3) * 2;
                float v0 = acc[mi][ni][rr * 2 + 0];
                float v1 = acc[mi][ni][rr * 2 + 1];
                if (MODE == 0) {
                    const int which = cc >> 10;
                    const int nn = cc & 1023;
                    const float* bp = (which == 0) ? bias0 : (which == 1 ? bias1 : bias2);
                    const int h = nn >> 6, hd = nn & 63;
                    float* dst = Cf + (size_t)which * (M_ * D_) +
                                 ((size_t)(bt * H_ + h) * T_ + tt) * HD_ + hd;
                    float2 bv = *(const float2*)(bp + nn);
                    float2 o2 = {v0 + bv.x, v1 + bv.y};
                    *(float2*)dst = o2;
                } else if (MODE == 1) {
                    size_t idx = (size_t)m * Nout + cc;
                    float2 bv = *(const float2*)(bias0 + cc);
                    float2 rv = *(const float2*)(res + idx);
                    float2 o2 = {v0 + bv.x + rv.x, v1 + bv.y + rv.y};
                    *(float2*)(Cf + idx) = o2;
                } else {
                    size_t idx = (size_t)m * Nout + cc;
                    float2 bv = *(const float2*)(bias0 + cc);
                    float a0 = fmaxf(v0 + bv.x, 0.f);
                    float a1 = fmaxf(v1 + bv.y, 0.f);
                    __nv_bfloat16 h0 = __float2bfloat16_rn(a0);
                    __nv_bfloat16 h1 = __float2bfloat16_rn(a1);
                    __nv_bfloat162 hh; hh.x = h0; hh.y = h1;
                    __nv_bfloat162 ll;
                    ll.x = __float2bfloat16_rn(a0 - __bfloat162float(h0));
                    ll.y = __float2bfloat16_rn(a1 - __bfloat162float(h1));
                    *(__nv_bfloat162*)(Chi + idx) = hh;
                    *(__nv_bfloat162*)(Clo + idx) = ll;
                }
            }
        }
    }
}

// ---------------- flash attention (fp32), writes bf16 pair -------------------
__global__ __launch_bounds__(256)
void attn_k(const float* __restrict__ q, const float* __restrict__ k,
            const float* __restrict__ v,
            __nv_bfloat16* __restrict__ ohi, __nv_bfloat16* __restrict__ olo) {
    __shared__ float Ks[64][68];
    __shared__ float Vs[64][68];
    __shared__ float qs[8][64];

    int bh   = blockIdx.y;
    int warp = threadIdx.x >> 5;
    int lane = threadIdx.x & 31;
    int qi   = blockIdx.x * 8 + warp;
    int b = bh >> 4, h = bh & 15;

    const float* kb = k + (size_t)bh * T_ * HD_;
    const float* vb = v + (size_t)bh * T_ * HD_;
    const float* qp = q + ((size_t)bh * T_ + qi) * HD_;
    qs[warp][lane]      = qp[lane];
    qs[warp][lane + 32] = qp[lane + 32];

    float mx = -1e30f, l = 0.f, o0 = 0.f, o1 = 0.f;
    const int qmax = blockIdx.x * 8 + 7;
    const int ntiles = (qmax >> 6) + 1;

    for (int t0 = 0; t0 < ntiles; t0++) {
        int j0 = t0 * 64;
        __syncthreads();
        #pragma unroll
        for (int i = 0; i < 4; i++) {
            int f = threadIdx.x + 256 * i;
            int r = f >> 4, c = (f & 15) * 4;
            *(float4*)&Ks[r][c] = *(const float4*)(kb + (size_t)(j0 + r) * HD_ + c);
            *(float4*)&Vs[r][c] = *(const float4*)(vb + (size_t)(j0 + r) * HD_ + c);
        }
        __syncthreads();

        #pragma unroll
        for (int hh = 0; hh < 2; hh++) {
            int jbase = j0 + hh * 32;
            if (jbase > qi) break;
            int j = jbase + lane;
            float s = 0.f;
            const float* kr = &Ks[hh * 32 + lane][0];
            const float* qr = &qs[warp][0];
            #pragma unroll
            for (int d = 0; d < 64; d += 4) {
                float4 kv = *(const float4*)(kr + d);
                float4 qv = *(const float4*)(qr + d);
                s += qv.x * kv.x + qv.y * kv.y + qv.z * kv.z + qv.w * kv.w;
            }
            s *= 0.125f;
            if (j > qi) s = -1e30f;

            float mt = s;
            #pragma unroll
            for (int off = 16; off; off >>= 1)
                mt = fmaxf(mt, __shfl_xor_sync(0xffffffffu, mt, off));
            float mn   = fmaxf(mx, mt);
            float corr = __expf(mx - mn);
            float e    = __expf(s - mn);
            float es   = e;
            #pragma unroll
            for (int off = 16; off; off >>= 1)
                es += __shfl_xor_sync(0xffffffffu, es, off);
            l  = l * corr + es;
            o0 *= corr; o1 *= corr;
            mx = mn;

            #pragma unroll
            for (int jj = 0; jj < 32; jj++) {
                float ej = __shfl_sync(0xffffffffu, e, jj);
                o0 += ej * Vs[hh * 32 + jj][lane];
                o1 += ej * Vs[hh * 32 + jj][lane + 32];
            }
        }
    }

    float invl = 1.0f / l;
    float v0 = o0 * invl, v1 = o1 * invl;
    size_t base = ((size_t)(b * T_ + qi)) * D_ + h * HD_;
    __nv_bfloat16 h0 = __float2bfloat16_rn(v0);
    __nv_bfloat16 h1 = __float2bfloat16_rn(v1);
    ohi[base + lane]      = h0;
    ohi[base + lane + 32] = h1;
    olo[base + lane]      = __float2bfloat16_rn(v0 - __bfloat162float(h0));
    olo[base + lane + 32] = __float2bfloat16_rn(v1 - __bfloat162float(h1));
}

// ---------------- head GEMV ----------------------------------------------------
__global__ __launch_bounds__(256)
void head_k(const float* __restrict__ hf, const float* __restrict__ W,
            const float* __restrict__ hb, float* __restrict__ out) {
    __shared__ float s0[D_];
    __shared__ float s1[D_];
    for (int i = threadIdx.x; i < D_; i += 256) { s0[i] = hf[i]; s1[i] = hf[D_ + i]; }
    __syncthreads();
    int vcol = blockIdx.x * 256 + threadIdx.x;
    float a0 = 0.f, a1 = 0.f;
    #pragma unroll 4
    for (int d = 0; d < D_; d++) {
        float wv = W[(size_t)d * V_ + vcol];
        a0 += s0[d] * wv;
        a1 += s1[d] * wv;
    }
    float bb = hb[vcol];
    out[vcol]      = a0 + bb;
    out[V_ + vcol] = a1 + bb;
}

// ---------------- launch --------------------------------------------------
extern "C" void kernel_launch(void* const* d_in, const int* in_sizes, int n_in,
                              void* d_out, int out_size) {
    const int*   idx    = (const int*)  d_in[0];
    const float* tok    = (const float*)d_in[1];
    const float* pos    = (const float*)d_in[2];
    const float* ln1w   = (const float*)d_in[3];
    const float* ln1b   = (const float*)d_in[4];
    const float* qw     = (const float*)d_in[5];
    const float* qb     = (const float*)d_in[6];
    const float* kw     = (const float*)d_in[7];
    const float* kbi    = (const float*)d_in[8];
    const float* vw     = (const float*)d_in[9];
    const float* vb     = (const float*)d_in[10];
    const float* ow     = (const float*)d_in[11];
    const float* ob     = (const float*)d_in[12];
    const float* ln2w   = (const float*)d_in[13];
    const float* ln2b   = (const float*)d_in[14];
    const float* f1w    = (const float*)d_in[15];
    const float* f1b    = (const float*)d_in[16];
    const float* f2w    = (const float*)d_in[17];
    const float* f2b    = (const float*)d_in[18];
    const float* lnfw   = (const float*)d_in[19];
    const float* lnfb   = (const float*)d_in[20];
    const float* headw  = (const float*)d_in[21];
    const float* headb  = (const float*)d_in[22];

    float *x, *qkv, *hf;
    __nv_bfloat16 *wqkvh, *wqkvl, *woh, *wol, *wf1h, *wf1l, *wf2h, *wf2l;
    __nv_bfloat16 *hhi, *hlo, *ohi, *olo, *ffhi, *fflo;
    cudaGetSymbolAddress((void**)&x,     g_x);
    cudaGetSymbolAddress((void**)&qkv,   g_qkv);
    cudaGetSymbolAddress((void**)&hf,    g_hf);
    cudaGetSymbolAddress((void**)&wqkvh, g_wqkv_h);
    cudaGetSymbolAddress((void**)&wqkvl, g_wqkv_l);
    cudaGetSymbolAddress((void**)&woh,   g_wo_h);
    cudaGetSymbolAddress((void**)&wol,   g_wo_l);
    cudaGetSymbolAddress((void**)&wf1h,  g_wf1_h);
    cudaGetSymbolAddress((void**)&wf1l,  g_wf1_l);
    cudaGetSymbolAddress((void**)&wf2h,  g_wf2_h);
    cudaGetSymbolAddress((void**)&wf2l,  g_wf2_l);
    cudaGetSymbolAddress((void**)&hhi,   g_hhi);
    cudaGetSymbolAddress((void**)&hlo,   g_hlo);
    cudaGetSymbolAddress((void**)&ohi,   g_ohi);
    cudaGetSymbolAddress((void**)&olo,   g_olo);
    cudaGetSymbolAddress((void**)&ffhi,  g_ffhi);
    cudaGetSymbolAddress((void**)&fflo,  g_fflo);

    cudaFuncSetAttribute(gemm_tc<0>, cudaFuncAttributeMaxDynamicSharedMemorySize, GSMEM);
    cudaFuncSetAttribute(gemm_tc<1>, cudaFuncAttributeMaxDynamicSharedMemorySize, GSMEM);
    cudaFuncSetAttribute(gemm_tc<2>, cudaFuncAttributeMaxDynamicSharedMemorySize, GSMEM);

    const long MEG = 1024 * 1024;
    dim3 gQKV(24, 16), gDD(8, 16), gF1(32, 16);
    dim3 gAt(T_ / 8, B_ * H_);

    // launch 0
    embed_k<<<M_, 256>>>(idx, tok, pos);
    // launches 1-3: QKV weight conversion (all layers)
    convw2<<<dim3(1024, L_), 256>>>(qw, wqkvh, wqkvl, 10, 1023, 3 * D_, 0,    MEG, 3 * MEG);
    convw2<<<dim3(1024, L_), 256>>>(kw, wqkvh, wqkvl, 10, 1023, 3 * D_, 1024, MEG, 3 * MEG);
    convw2<<<dim3(1024, L_), 256>>>(vw, wqkvh, wqkvl, 10, 1023, 3 * D_, 2048, MEG, 3 * MEG);
    // launch 4: LN1 layer 0
    ln_k<<<M_, 256>>>(x, D_, ln1w, ln1b, hhi, hlo, nullptr);
    // launch 5: QKV GEMM layer 0  (profiled by ncu -s 5 -c 1)
    gemm_tc<0><<<gQKV, 256, GSMEM>>>(hhi, hlo, wqkvh, wqkvl,
                                     qb, kbi, vb,
                                     nullptr, qkv, nullptr, nullptr, D_, 3 * D_, 0);
    // remaining conversions
    convw2<<<dim3(1024, L_), 256>>>(ow,  woh,  wol,  10, 1023, D_,  0, MEG,     MEG);
    convw2<<<dim3(4096, L_), 256>>>(f1w, wf1h, wf1l, 12, 4095, FF_, 0, 4 * MEG, 4 * MEG);
    convw2<<<dim3(4096, L_), 256>>>(f2w, wf2h, wf2l, 10, 1023, D_,  0, 4 * MEG, 4 * MEG);

    for (int l = 0; l < L_; l++) {
        size_t wq3 = (size_t)l * 3 * MEG;
        size_t wdd = (size_t)l * MEG;
        size_t wff = (size_t)l * 4 * MEG;

        if (l > 0) {
            ln_k<<<M_, 256>>>(x, D_, ln1w + l * D_, ln1b + l * D_, hhi, hlo, nullptr);
            gemm_tc<0><<<gQKV, 256, GSMEM>>>(hhi, hlo, wqkvh + wq3, wqkvl + wq3,
                                             qb + l * D_, kbi + l * D_, vb + l * D_,
                                             nullptr, qkv, nullptr, nullptr, D_, 3 * D_, 0);
        }

        attn_k<<<gAt, 256>>>(qkv, qkv + M_ * D_, qkv + 2 * M_ * D_, ohi, olo);

        gemm_tc<1><<<gDD, 256, GSMEM>>>(ohi, olo, woh + wdd, wol + wdd,
                                        ob + l * D_, nullptr, nullptr,
                                        x, x, nullptr, nullptr, D_, D_, D_);

        ln_k<<<M_, 256>>>(x, D_, ln2w + l * D_, ln2b + l * D_, hhi, hlo, nullptr);

        gemm_tc<2><<<gF1, 256, GSMEM>>>(hhi, hlo, wf1h + wff, wf1l + wff,
                                        f1b + l * FF_, nullptr, nullptr,
                                        nullptr, nullptr, ffhi, fflo, D_, FF_, FF_);

        gemm_tc<1><<<gDD, 256, GSMEM>>>(ffhi, fflo, wf2h + wff, wf2l + wff,
                                        f2b + l * D_, nullptr, nullptr,
                                        x, x, nullptr, nullptr, FF_, D_, D_);
    }

    ln_k<<<B_, 256>>>(x + (size_t)(T_ - 1) * D_, (long)T_ * D_, lnfw, lnfb,
                      nullptr, nullptr, hf);

    head_k<<<V_ / 256, 256>>>(hf, headw, headb, (float*)d_out);
}

// round 6
// speedup vs baseline: 5.3455x; 2.0756x over previous
#include <cuda_runtime.h>
#include <cuda_fp16.h>
#include <cstdint>

#define D_  1024
#define H_  16
#define HD_ 64
#define T_  1024
#define B_  2
#define L_  8
#define FF_ 4096
#define V_  32000
#define M_  (B_ * T_)   // 2048 rows

// ---------------- scratch (device globals) ----------------------------------
// weights: K-major [K][N] fp16 hi/lo pairs
__device__ __half g_wqkv_h[(size_t)L_ * D_ * 3 * D_], g_wqkv_l[(size_t)L_ * D_ * 3 * D_];
__device__ __half g_wo_h  [(size_t)L_ * D_ * D_],     g_wo_l  [(size_t)L_ * D_ * D_];
__device__ __half g_wf1_h [(size_t)L_ * D_ * FF_],    g_wf1_l [(size_t)L_ * D_ * FF_];
__device__ __half g_wf2_h [(size_t)L_ * FF_ * D_],    g_wf2_l [(size_t)L_ * FF_ * D_];
__device__ float g_x [M_ * D_];
// attention operands (fp16 pairs); K stored transposed [BH][HD][T]
__device__ __half g_qh[M_ * D_], g_ql[M_ * D_];
__device__ __half g_kh[M_ * D_], g_kl[M_ * D_];
__device__ __half g_vh[M_ * D_], g_vl[M_ * D_];
// single-fp16 activations
__device__ __half g_hh [M_ * D_];
__device__ __half g_oh [M_ * D_];
__device__ __half g_ffh[M_ * FF_];
__device__ float g_hf[B_ * D_];

// ---------------- ptx helpers ------------------------------------------------
__device__ __forceinline__ uint32_t smem_u32(const void* p) {
    uint32_t a;
    asm("{ .reg .u64 t; cvta.to.shared.u64 t, %1; cvt.u32.u64 %0, t; }" : "=r"(a) : "l"(p));
    return a;
}
#define LDSM4(r, a) \
    asm volatile("ldmatrix.sync.aligned.m8n8.x4.shared.b16 {%0,%1,%2,%3}, [%4];" \
        : "=r"((r)[0]), "=r"((r)[1]), "=r"((r)[2]), "=r"((r)[3]) : "r"(a))
#define LDSM4T(r, a) \
    asm volatile("ldmatrix.sync.aligned.m8n8.x4.trans.shared.b16 {%0,%1,%2,%3}, [%4];" \
        : "=r"((r)[0]), "=r"((r)[1]), "=r"((r)[2]), "=r"((r)[3]) : "r"(a))
#define MMA_F16(c, a, b) \
    asm volatile("mma.sync.aligned.m16n8k16.row.col.f32.f16.f16.f32 " \
        "{%0,%1,%2,%3}, {%4,%5,%6,%7}, {%8,%9}, {%0,%1,%2,%3};" \
        : "+f"((c)[0]), "+f"((c)[1]), "+f"((c)[2]), "+f"((c)[3]) \
        : "r"((a)[0]), "r"((a)[1]), "r"((a)[2]), "r"((a)[3]), "r"((b)[0]), "r"((b)[1]))
#define CP_ASYNC16(d, g) \
    asm volatile("cp.async.cg.shared.global [%0], [%1], 16;" :: "r"(d), "l"(g))
#define CP_COMMIT() asm volatile("cp.async.commit_group;" ::: "memory")
#define CP_WAIT0()  asm volatile("cp.async.wait_group 0;" ::: "memory")
#define CP_WAIT1()  asm volatile("cp.async.wait_group 1;" ::: "memory")

__device__ __forceinline__ uint32_t pack_h2(float a, float b) {
    __half2 h; h.x = __float2half_rn(a); h.y = __float2half_rn(b);
    return *(uint32_t*)&h;
}

// ---------------- embedding ---------------------------------------------------
__global__ void embed_k(const int* __restrict__ idx,
                        const float* __restrict__ tok,
                        const float* __restrict__ pos) {
    int m = blockIdx.x;
    int t = m & (T_ - 1);
    const float* te = tok + (size_t)idx[m] * D_;
    const float* pe = pos + (size_t)t * D_;
    float* xr = g_x + (size_t)m * D_;
    for (int d = threadIdx.x; d < D_; d += blockDim.x)
        xr[d] = te[d] + pe[d];
}

// ---------------- weight convert: fp32 -> fp16 hi/lo (elementwise) ------------
__global__ void convw2(const float* __restrict__ W,
                       __half* __restrict__ hi, __half* __restrict__ lo) {
    size_t idx = ((size_t)blockIdx.x * 256 + threadIdx.x) * 4;
    float4 v = *(const float4*)(W + idx);
    union { uint2 u; __half b[4]; } ph, pl;
    float vv[4] = {v.x, v.y, v.z, v.w};
    #pragma unroll
    for (int i = 0; i < 4; i++) {
        __half h = __float2half_rn(vv[i]);
        ph.b[i] = h;
        pl.b[i] = __float2half_rn(vv[i] - __half2float(h));
    }
    *(uint2*)(hi + idx) = ph.u;
    *(uint2*)(lo + idx) = pl.u;
}

// ---------------- layernorm: writes single fp16 (and/or fp32) -----------------
__global__ void ln_k(const float* __restrict__ in, long in_stride,
                     const float* __restrict__ w, const float* __restrict__ b,
                     __half* __restrict__ oh, float* __restrict__ of) {
    const float* row = in + (size_t)blockIdx.x * in_stride;
    int tid = threadIdx.x;
    float vals[4];
    float s = 0.f;
    #pragma unroll
    for (int i = 0; i < 4; i++) { vals[i] = row[tid + 256 * i]; s += vals[i]; }

    __shared__ float red[8];
    int lane = tid & 31, warp = tid >> 5;
    #pragma unroll
    for (int off = 16; off; off >>= 1) s += __shfl_xor_sync(0xffffffffu, s, off);
    if (lane == 0) red[warp] = s;
    __syncthreads();
    float tot = 0.f;
    #pragma unroll
    for (int i = 0; i < 8; i++) tot += red[i];
    float mean = tot * (1.0f / D_);

    float s2 = 0.f;
    #pragma unroll
    for (int i = 0; i < 4; i++) { float d = vals[i] - mean; s2 += d * d; }
    __syncthreads();
    #pragma unroll
    for (int off = 16; off; off >>= 1) s2 += __shfl_xor_sync(0xffffffffu, s2, off);
    if (lane == 0) red[warp] = s2;
    __syncthreads();
    float tot2 = 0.f;
    #pragma unroll
    for (int i = 0; i < 8; i++) tot2 += red[i];
    float inv = rsqrtf(tot2 * (1.0f / D_) + 1e-5f);

    size_t base = (size_t)blockIdx.x * D_;
    #pragma unroll
    for (int i = 0; i < 4; i++) {
        int d = tid + 256 * i;
        float v = (vals[i] - mean) * inv * w[d] + b[d];
        if (of) of[base + d] = v;
        if (oh) oh[base + d] = __float2half_rn(v);
    }
}

// ---------------- mma.sync fp16 GEMM, W hi/lo 2-pass, 128x128x32, 3-stage -----
// A: [M,K] row-major single fp16. B: [K,N] row-major fp16 pair.
// MODE 0: QKV: split/permute into q/k/v fp16 pairs (K transposed layout)
// MODE 1: fp32 out = acc + bias0 + res
// MODE 2: fp16 out = relu(acc + bias0)
#define A_TILE   10240                       // 128 rows x 80B
#define B_TILE   8704                        // 32 rows x 272B
#define STAGE_B  (A_TILE + 2 * B_TILE)       // 27648
#define GSMEM    (3 * STAGE_B)               // 82944

template<int MODE>
__global__ __launch_bounds__(256, 1)
void gemm_tc(const __half* __restrict__ A,
             const __half* __restrict__ Bhi, const __half* __restrict__ Blo,
             const float* __restrict__ bias0, const float* __restrict__ bias1,
             const float* __restrict__ bias2, const float* __restrict__ res,
             float* __restrict__ Cf, __half* __restrict__ Ch,
             __half* p0, __half* p1, __half* p2, __half* p3, __half* p4, __half* p5,
             int Kdim, int Nb, int Nout) {
    extern __shared__ char smem[];
    const uint32_t sb = smem_u32(smem);
    const int tid = threadIdx.x, lane = tid & 31, wid = tid >> 5;
    const int bm = blockIdx.y * 128, bn = blockIdx.x * 128;
    const int wm = wid & 1, wn = wid >> 1;     // warp tile: 64 x 32

    const int KT = Kdim >> 5;

    auto load_stage = [&](int ss) {
        const uint32_t dst = sb + (ss % 3) * STAGE_B;
        const int kg = ss * 32;
        #pragma unroll
        for (int i = 0; i < 2; i++) {
            int ch = tid + 256 * i;            // 0..511
            int r = ch >> 2;
            const __half* ga = A + (size_t)(bm + r) * Kdim + kg + (ch & 3) * 8;
            CP_ASYNC16(dst + r * 80 + (ch & 3) * 16, ga);
        }
        #pragma unroll
        for (int i = 0; i < 2; i++) {
            int ch = tid + 256 * i;
            int r = ch >> 4, c = (ch & 15) * 8;
            const __half* gb = Bhi + (size_t)(kg + r) * Nb + bn + c;
            const __half* gl = Blo + (size_t)(kg + r) * Nb + bn + c;
            uint32_t db = dst + A_TILE + r * 272 + (ch & 15) * 16;
            CP_ASYNC16(db, gb);
            CP_ASYNC16(db + B_TILE, gl);
        }
    };

    load_stage(0); CP_COMMIT();
    load_stage(1); CP_COMMIT();

    float acc[4][4][4] = {};

    for (int s = 0; s < KT; s++) {
        if (s == KT - 1) { CP_WAIT0(); } else { CP_WAIT1(); }
        __syncthreads();
        if (s + 2 < KT) { load_stage(s + 2); CP_COMMIT(); }

        const uint32_t base = sb + (s % 3) * STAGE_B;
        #pragma unroll
        for (int ks = 0; ks < 2; ks++) {
            uint32_t ah[4][4], bh[2][4], bl[2][4];
            #pragma unroll
            for (int mi = 0; mi < 4; mi++) {
                uint32_t ra = base + (wm * 64 + mi * 16 + (lane & 15)) * 80
                            + ks * 32 + (lane >> 4) * 16;
                LDSM4(ah[mi], ra);
            }
            #pragma unroll
            for (int g = 0; g < 2; g++) {
                uint32_t rb = base + A_TILE + (ks * 16 + (lane & 15)) * 272
                            + (wn * 32 + g * 16) * 2 + (lane >> 4) * 16;
                LDSM4T(bh[g], rb);
                LDSM4T(bl[g], rb + B_TILE);
            }
            #pragma unroll
            for (int mi = 0; mi < 4; mi++)
                #pragma unroll
                for (int ni = 0; ni < 4; ni++) {
                    const uint32_t* bhp = &bh[ni >> 1][(ni & 1) * 2];
                    const uint32_t* blp = &bl[ni >> 1][(ni & 1) * 2];
                    MMA_F16(acc[mi][ni], ah[mi], bhp);
                    MMA_F16(acc[mi][ni], ah[mi], blp);
                }
        }
        __syncthreads();
    }

    // epilogue
    #pragma unroll
    for (int mi = 0; mi < 4; mi++) {
        const int r0 = bm + wm * 64 + mi * 16 + (lane >> 2);
        #pragma unroll
        for (int rr = 0; rr < 2; rr++) {
            const int m = r0 + rr * 8;
            const int bt = m >> 10, tt = m & (T_ - 1);
            #pragma unroll
            for (int ni = 0; ni < 4; ni++) {
                const int cc = bn + wn * 32 + ni * 8 + (lane & 3) * 2;
                float v0 = acc[mi][ni][rr * 2 + 0];
                float v1 = acc[mi][ni][rr * 2 + 1];
                if (MODE == 0) {
                    const int which = cc >> 10;
                    const int nn = cc & 1023;
                    const float* bp = (which == 0) ? bias0 : (which == 1 ? bias1 : bias2);
                    const int h = nn >> 6, hd = nn & 63;
                    const int bh_ = bt * H_ + h;
                    v0 += bp[nn]; v1 += bp[nn + 1];
                    if (which == 0) { v0 *= 0.125f; v1 *= 0.125f; }
                    __half h0 = __float2half_rn(v0), h1 = __float2half_rn(v1);
                    __half l0 = __float2half_rn(v0 - __half2float(h0));
                    __half l1 = __float2half_rn(v1 - __half2float(h1));
                    if (which == 1) {
                        // K transposed: [bh][hd][T]
                        size_t o0 = ((size_t)bh_ * HD_ + hd) * T_ + tt;
                        p2[o0] = h0; p2[o0 + T_] = h1;
                        p3[o0] = l0; p3[o0 + T_] = l1;
                    } else {
                        size_t o = ((size_t)bh_ * T_ + tt) * HD_ + hd;
                        __half2 hh; hh.x = h0; hh.y = h1;
                        __half2 ll; ll.x = l0; ll.y = l1;
                        if (which == 0) { *(__half2*)(p0 + o) = hh; *(__half2*)(p1 + o) = ll; }
                        else            { *(__half2*)(p4 + o) = hh; *(__half2*)(p5 + o) = ll; }
                    }
                } else if (MODE == 1) {
                    size_t idx = (size_t)m * Nout + cc;
                    float2 bv = *(const float2*)(bias0 + cc);
                    float2 rv = *(const float2*)(res + idx);
                    float2 o2 = {v0 + bv.x + rv.x, v1 + bv.y + rv.y};
                    *(float2*)(Cf + idx) = o2;
                } else {
                    size_t idx = (size_t)m * Nout + cc;
                    float2 bv = *(const float2*)(bias0 + cc);
                    __half2 hh;
                    hh.x = __float2half_rn(fmaxf(v0 + bv.x, 0.f));
                    hh.y = __float2half_rn(fmaxf(v1 + bv.y, 0.f));
                    *(__half2*)(Ch + idx) = hh;
                }
            }
        }
    }
}

// ---------------- tensor-core flash attention ---------------------------------
// Grid (T/64, BH), 128 threads (4 warps; warp owns 16 query rows).
// Q [BH,T,HD] pair (pre-scaled), K [BH,HD,T] pair, V [BH,T,HD] pair.
// Output: single fp16 [M, D] (proj GEMM input).
#define APAD 72
#define ATILE_H (64 * APAD)          // halves per tile
#define ATT_SMEM (6 * ATILE_H * 2)   // 55296 bytes

__global__ __launch_bounds__(128)
void attn_k(const __half* __restrict__ qh, const __half* __restrict__ ql,
            const __half* __restrict__ kh, const __half* __restrict__ kl,
            const __half* __restrict__ vh, const __half* __restrict__ vl,
            __half* __restrict__ oh) {
    extern __shared__ __half as_[];
    __half* Qh = as_;
    __half* Ql = Qh + ATILE_H;
    __half* Kh = Ql + ATILE_H;
    __half* Kl = Kh + ATILE_H;
    __half* Vh = Kl + ATILE_H;
    __half* Vl = Vh + ATILE_H;

    const int tid = threadIdx.x, lane = tid & 31, warp = tid >> 5;
    const int bh = blockIdx.y, q0 = blockIdx.x * 64;
    const int b = bh >> 4, h = bh & 15;

    // load Q tile (64 x 64 halves, rows q0..q0+63)
    #pragma unroll
    for (int i = 0; i < 4; i++) {
        int ch = tid + 128 * i;           // 512 chunks of 8 halves
        int r = ch >> 3, c = (ch & 7) * 8;
        size_t g = ((size_t)bh * T_ + q0 + r) * HD_ + c;
        *(uint4*)&Qh[r * APAD + c] = *(const uint4*)(qh + g);
        *(uint4*)&Ql[r * APAD + c] = *(const uint4*)(ql + g);
    }
    __syncthreads();

    // Q fragments
    uint32_t aq_h[4][4], aq_l[4][4];
    const uint32_t qbase = smem_u32(Qh);
    #pragma unroll
    for (int kf = 0; kf < 4; kf++) {
        uint32_t ra = qbase + ((warp * 16 + (lane & 15)) * APAD + kf * 16 + (lane >> 4) * 8) * 2;
        LDSM4(aq_h[kf], ra);
        LDSM4(aq_l[kf], ra + ATILE_H * 2);
    }

    float mx[2] = {-1e30f, -1e30f}, lsum[2] = {0.f, 0.f};
    float oacc[8][4] = {};

    const uint32_t kbase = smem_u32(Kh);
    const uint32_t vbase = smem_u32(Vh);
    const int ntiles = blockIdx.x + 1;

    for (int jt = 0; jt < ntiles; jt++) {
        const int j0 = jt * 64;
        __syncthreads();
        #pragma unroll
        for (int i = 0; i < 4; i++) {
            int ch = tid + 128 * i;
            int r = ch >> 3, c = (ch & 7) * 8;
            size_t gk = ((size_t)bh * HD_ + r) * T_ + j0 + c;
            size_t gv = ((size_t)bh * T_ + j0 + r) * HD_ + c;
            *(uint4*)&Kh[r * APAD + c] = *(const uint4*)(kh + gk);
            *(uint4*)&Kl[r * APAD + c] = *(const uint4*)(kl + gk);
            *(uint4*)&Vh[r * APAD + c] = *(const uint4*)(vh + gv);
            *(uint4*)&Vl[r * APAD + c] = *(const uint4*)(vl + gv);
        }
        __syncthreads();

        // scores: S = Q . K^T (3-pass split)
        float sacc[8][4] = {};
        #pragma unroll
        for (int kf = 0; kf < 4; kf++) {
            #pragma unroll
            for (int g = 0; g < 4; g++) {
                uint32_t kb2[4], kl2[4];
                uint32_t rb = kbase + ((kf * 16 + (lane & 15)) * APAD + g * 16 + (lane >> 4) * 8) * 2;
                LDSM4T(kb2, rb);
                LDSM4T(kl2, rb + ATILE_H * 2);
                MMA_F16(sacc[2 * g],     aq_h[kf], kb2);
                MMA_F16(sacc[2 * g + 1], aq_h[kf], kb2 + 2);
                MMA_F16(sacc[2 * g],     aq_h[kf], kl2);
                MMA_F16(sacc[2 * g + 1], aq_h[kf], kl2 + 2);
                MMA_F16(sacc[2 * g],     aq_l[kf], kb2);
                MMA_F16(sacc[2 * g + 1], aq_l[kf], kb2 + 2);
            }
        }

        // causal mask on diagonal tile
        if (jt == blockIdx.x) {
            const int rbase = q0 + warp * 16 + (lane >> 2);
            #pragma unroll
            for (int nf = 0; nf < 8; nf++) {
                int c0 = j0 + nf * 8 + (lane & 3) * 2;
                if (c0     > rbase)     sacc[nf][0] = -1e30f;
                if (c0 + 1 > rbase)     sacc[nf][1] = -1e30f;
                if (c0     > rbase + 8) sacc[nf][2] = -1e30f;
                if (c0 + 1 > rbase + 8) sacc[nf][3] = -1e30f;
            }
        }

        // online softmax per row-half
        #pragma unroll
        for (int hf = 0; hf < 2; hf++) {
            float mnew = -1e30f;
            #pragma unroll
            for (int nf = 0; nf < 8; nf++)
                mnew = fmaxf(mnew, fmaxf(sacc[nf][hf * 2], sacc[nf][hf * 2 + 1]));
            mnew = fmaxf(mnew, __shfl_xor_sync(0xffffffffu, mnew, 1));
            mnew = fmaxf(mnew, __shfl_xor_sync(0xffffffffu, mnew, 2));
            float mn = fmaxf(mx[hf], mnew);
            float corr = __expf(mx[hf] - mn);
            float ps = 0.f;
            #pragma unroll
            for (int nf = 0; nf < 8; nf++) {
                float s0 = __expf(sacc[nf][hf * 2]     - mn);
                float s1 = __expf(sacc[nf][hf * 2 + 1] - mn);
                sacc[nf][hf * 2] = s0; sacc[nf][hf * 2 + 1] = s1;
                ps += s0 + s1;
            }
            ps += __shfl_xor_sync(0xffffffffu, ps, 1);
            ps += __shfl_xor_sync(0xffffffffu, ps, 2);
            lsum[hf] = lsum[hf] * corr + ps;
            #pragma unroll
            for (int nf = 0; nf < 8; nf++) {
                oacc[nf][hf * 2] *= corr; oacc[nf][hf * 2 + 1] *= corr;
            }
            mx[hf] = mn;
        }

        // pack P into fp16 hi/lo A-fragments
        uint32_t pah[4][4], pal[4][4];
        #pragma unroll
        for (int kf = 0; kf < 4; kf++) {
            const float* s0 = sacc[2 * kf];
            const float* s1 = sacc[2 * kf + 1];
            float e[8] = {s0[0], s0[1], s0[2], s0[3], s1[0], s1[1], s1[2], s1[3]};
            float hi[8], lo[8];
            #pragma unroll
            for (int i = 0; i < 8; i++) {
                __half hh = __float2half_rn(e[i]);
                hi[i] = __half2float(hh);
                lo[i] = e[i] - hi[i];
            }
            #pragma unroll
            for (int i = 0; i < 4; i++) {
                pah[kf][i] = pack_h2(hi[2 * i], hi[2 * i + 1]);
                pal[kf][i] = pack_h2(lo[2 * i], lo[2 * i + 1]);
            }
        }

        // O += P . V  (3-pass split)
        #pragma unroll
        for (int kf = 0; kf < 4; kf++) {
            #pragma unroll
            for (int g = 0; g < 4; g++) {
                uint32_t vb2[4], vl2[4];
                uint32_t rb = vbase + ((kf * 16 + (lane & 15)) * APAD + g * 16 + (lane >> 4) * 8) * 2;
                LDSM4T(vb2, rb);
                LDSM4T(vl2, rb + ATILE_H * 2);
                MMA_F16(oacc[2 * g],     pah[kf], vb2);
                MMA_F16(oacc[2 * g + 1], pah[kf], vb2 + 2);
                MMA_F16(oacc[2 * g],     pah[kf], vl2);
                MMA_F16(oacc[2 * g + 1], pah[kf], vl2 + 2);
                MMA_F16(oacc[2 * g],     pal[kf], vb2);
                MMA_F16(oacc[2 * g + 1], pal[kf], vb2 + 2);
            }
        }
    }

    // epilogue: normalize and store single fp16 to [M, D]
    #pragma unroll
    for (int hf = 0; hf < 2; hf++) {
        float inv = 1.0f / lsum[hf];
        int row = q0 + warp * 16 + (lane >> 2) + hf * 8;
        size_t rbase = ((size_t)(b * T_ + row)) * D_ + h * HD_;
        #pragma unroll
        for (int nf = 0; nf < 8; nf++) {
            int col = nf * 8 + (lane & 3) * 2;
            __half2 o2;
            o2.x = __float2half_rn(oacc[nf][hf * 2]     * inv);
            o2.y = __float2half_rn(oacc[nf][hf * 2 + 1] * inv);
            *(__half2*)(oh + rbase + col) = o2;
        }
    }
}

// ---------------- head GEMV ----------------------------------------------------
__global__ __launch_bounds__(256)
void head_k(const float* __restrict__ hf, const float* __restrict__ W,
            const float* __restrict__ hb, float* __restrict__ out) {
    __shared__ float s0[D_];
    __shared__ float s1[D_];
    for (int i = threadIdx.x; i < D_; i += 256) { s0[i] = hf[i]; s1[i] = hf[D_ + i]; }
    __syncthreads();
    int vcol = blockIdx.x * 256 + threadIdx.x;
    float a0 = 0.f, a1 = 0.f;
    #pragma unroll 4
    for (int d = 0; d < D_; d++) {
        float wv = W[(size_t)d * V_ + vcol];
        a0 += s0[d] * wv;
        a1 += s1[d] * wv;
    }
    float bb = hb[vcol];
    out[vcol]      = a0 + bb;
    out[V_ + vcol] = a1 + bb;
}

// ---------------- QKV->3N merge helper: interleave conversions ----------------
// qw/kw/vw are [L][D][D]; dest wqkv [L][D][3D] hi/lo. One kernel per source.
__global__ void convqkv(const float* __restrict__ W, int colOff,
                        __half* __restrict__ hi, __half* __restrict__ lo) {
    long z = blockIdx.y;
    long i4 = (long)blockIdx.x * 256 + threadIdx.x;
    long idx = i4 * 4;
    int k = (int)(idx >> 10);
    int n = (int)(idx & 1023);
    float4 v = *(const float4*)(W + z * (1 << 20) + idx);
    size_t d = (size_t)z * (3 << 20) + (size_t)k * (3 * D_) + colOff + n;
    union { uint2 u; __half b[4]; } ph, pl;
    float vv[4] = {v.x, v.y, v.z, v.w};
    #pragma unroll
    for (int i = 0; i < 4; i++) {
        __half h = __float2half_rn(vv[i]);
        ph.b[i] = h;
        pl.b[i] = __float2half_rn(vv[i] - __half2float(h));
    }
    *(uint2*)(hi + d) = ph.u;
    *(uint2*)(lo + d) = pl.u;
}

// ---------------- launch --------------------------------------------------
extern "C" void kernel_launch(void* const* d_in, const int* in_sizes, int n_in,
                              void* d_out, int out_size) {
    const int*   idx    = (const int*)  d_in[0];
    const float* tok    = (const float*)d_in[1];
    const float* pos    = (const float*)d_in[2];
    const float* ln1w   = (const float*)d_in[3];
    const float* ln1b   = (const float*)d_in[4];
    const float* qw     = (const float*)d_in[5];
    const float* qb     = (const float*)d_in[6];
    const float* kw     = (const float*)d_in[7];
    const float* kbi    = (const float*)d_in[8];
    const float* vw     = (const float*)d_in[9];
    const float* vb     = (const float*)d_in[10];
    const float* ow     = (const float*)d_in[11];
    const float* ob     = (const float*)d_in[12];
    const float* ln2w   = (const float*)d_in[13];
    const float* ln2b   = (const float*)d_in[14];
    const float* f1w    = (const float*)d_in[15];
    const float* f1b    = (const float*)d_in[16];
    const float* f2w    = (const float*)d_in[17];
    const float* f2b    = (const float*)d_in[18];
    const float* lnfw   = (const float*)d_in[19];
    const float* lnfb   = (const float*)d_in[20];
    const float* headw  = (const float*)d_in[21];
    const float* headb  = (const float*)d_in[22];

    float *x, *hf;
    __half *wqkvh, *wqkvl, *woh, *wol, *wf1h, *wf1l, *wf2h, *wf2l;
    __half *qh, *ql, *kh, *kl, *vh, *vl, *hh, *oh, *ffh;
    cudaGetSymbolAddress((void**)&x,     g_x);
    cudaGetSymbolAddress((void**)&hf,    g_hf);
    cudaGetSymbolAddress((void**)&wqkvh, g_wqkv_h);
    cudaGetSymbolAddress((void**)&wqkvl, g_wqkv_l);
    cudaGetSymbolAddress((void**)&woh,   g_wo_h);
    cudaGetSymbolAddress((void**)&wol,   g_wo_l);
    cudaGetSymbolAddress((void**)&wf1h,  g_wf1_h);
    cudaGetSymbolAddress((void**)&wf1l,  g_wf1_l);
    cudaGetSymbolAddress((void**)&wf2h,  g_wf2_h);
    cudaGetSymbolAddress((void**)&wf2l,  g_wf2_l);
    cudaGetSymbolAddress((void**)&qh,    g_qh);
    cudaGetSymbolAddress((void**)&ql,    g_ql);
    cudaGetSymbolAddress((void**)&kh,    g_kh);
    cudaGetSymbolAddress((void**)&kl,    g_kl);
    cudaGetSymbolAddress((void**)&vh,    g_vh);
    cudaGetSymbolAddress((void**)&vl,    g_vl);
    cudaGetSymbolAddress((void**)&hh,    g_hh);
    cudaGetSymbolAddress((void**)&oh,    g_oh);
    cudaGetSymbolAddress((void**)&ffh,   g_ffh);

    cudaFuncSetAttribute(gemm_tc<0>, cudaFuncAttributeMaxDynamicSharedMemorySize, GSMEM);
    cudaFuncSetAttribute(gemm_tc<1>, cudaFuncAttributeMaxDynamicSharedMemorySize, GSMEM);
    cudaFuncSetAttribute(gemm_tc<2>, cudaFuncAttributeMaxDynamicSharedMemorySize, GSMEM);
    cudaFuncSetAttribute(attn_k, cudaFuncAttributeMaxDynamicSharedMemorySize, ATT_SMEM);

    const long MEG = 1024 * 1024;
    dim3 gQKV(24, 16), gDD(8, 16), gF1(32, 16);
    dim3 gAt(T_ / 64, B_ * H_);

    embed_k<<<M_, 256>>>(idx, tok, pos);
    convqkv<<<dim3(1024, L_), 256>>>(qw, 0,    wqkvh, wqkvl);
    convqkv<<<dim3(1024, L_), 256>>>(kw, 1024, wqkvh, wqkvl);
    convqkv<<<dim3(1024, L_), 256>>>(vw, 2048, wqkvh, wqkvl);
    ln_k<<<M_, 256>>>(x, D_, ln1w, ln1b, hh, nullptr);
    gemm_tc<0><<<gQKV, 256, GSMEM>>>(hh, wqkvh, wqkvl,
                                     qb, kbi, vb, nullptr, nullptr, nullptr,
                                     qh, ql, kh, kl, vh, vl, D_, 3 * D_, 0);
    convw2<<<(L_ * MEG) / 1024, 256>>>(ow,  woh,  wol);
    convw2<<<(L_ * 4 * MEG) / 1024, 256>>>(f1w, wf1h, wf1l);
    convw2<<<(L_ * 4 * MEG) / 1024, 256>>>(f2w, wf2h, wf2l);

    for (int l = 0; l < L_; l++) {
        size_t wq3 = (size_t)l * 3 * MEG;
        size_t wdd = (size_t)l * MEG;
        size_t wff = (size_t)l * 4 * MEG;

        if (l > 0) {
            ln_k<<<M_, 256>>>(x, D_, ln1w + l * D_, ln1b + l * D_, hh, nullptr);
            gemm_tc<0><<<gQKV, 256, GSMEM>>>(hh, wqkvh + wq3, wqkvl + wq3,
                                             qb + l * D_, kbi + l * D_, vb + l * D_,
                                             nullptr, nullptr, nullptr,
                                             qh, ql, kh, kl, vh, vl, D_, 3 * D_, 0);
        }

        attn_k<<<gAt, 128, ATT_SMEM>>>(qh, ql, kh, kl, vh, vl, oh);

        gemm_tc<1><<<gDD, 256, GSMEM>>>(oh, woh + wdd, wol + wdd,
                                        ob + l * D_, nullptr, nullptr,
                                        x, x, nullptr,
                                        nullptr, nullptr, nullptr, nullptr, nullptr, nullptr,
                                        D_, D_, D_);

        ln_k<<<M_, 256>>>(x, D_, ln2w + l * D_, ln2b + l * D_, hh, nullptr);

        gemm_tc<2><<<gF1, 256, GSMEM>>>(hh, wf1h + wff, wf1l + wff,
                                        f1b + l * FF_, nullptr, nullptr,
                                        nullptr, nullptr, ffh,
                                        nullptr, nullptr, nullptr, nullptr, nullptr, nullptr,
                                        D_, FF_, FF_);

        gemm_tc<1><<<gDD, 256, GSMEM>>>(ffh, wf2h + wff, wf2l + wff,
                                        f2b + l * D_, nullptr, nullptr,
                                        x, x, nullptr,
                                        nullptr, nullptr, nullptr, nullptr, nullptr, nullptr,
                                        FF_, D_, D_);
    }

    ln_k<<<B_, 256>>>(x + (size_t)(T_ - 1) * D_, (long)T_ * D_, lnfw, lnfb,
                      nullptr, hf);

    head_k<<<V_ / 256, 256>>>(hf, headw, headb, (float*)d_out);
}

// round 7
// speedup vs baseline: 7.6758x; 1.4359x over previous
#include <cuda_runtime.h>
#include <cuda_fp16.h>
#include <cstdint>

#define D_  1024
#define H_  16
#define HD_ 64
#define T_  1024
#define B_  2
#define L_  8
#define FF_ 4096
#define V_  32000
#define M_  (B_ * T_)   // 2048 rows

// ---------------- scratch (device globals) ----------------------------------
// weights: K-major [K][N] single fp16
__device__ __half g_wqkv[(size_t)L_ * D_ * 3 * D_];
__device__ __half g_wo  [(size_t)L_ * D_ * D_];
__device__ __half g_wf1 [(size_t)L_ * D_ * FF_];
__device__ __half g_wf2 [(size_t)L_ * FF_ * D_];
__device__ float g_x [M_ * D_];
// attention operands; K stored transposed [BH][HD][T]
__device__ __half g_q[M_ * D_];
__device__ __half g_k[M_ * D_];
__device__ __half g_v[M_ * D_];
// single-fp16 activations
__device__ __half g_hh [M_ * D_];
__device__ __half g_oh [M_ * D_];
__device__ __half g_ffh[M_ * FF_];
__device__ float g_hf[B_ * D_];

// ---------------- ptx helpers ------------------------------------------------
__device__ __forceinline__ uint32_t smem_u32(const void* p) {
    uint32_t a;
    asm("{ .reg .u64 t; cvta.to.shared.u64 t, %1; cvt.u32.u64 %0, t; }" : "=r"(a) : "l"(p));
    return a;
}
#define LDSM4(r, a) \
    asm volatile("ldmatrix.sync.aligned.m8n8.x4.shared.b16 {%0,%1,%2,%3}, [%4];" \
        : "=r"((r)[0]), "=r"((r)[1]), "=r"((r)[2]), "=r"((r)[3]) : "r"(a))
#define LDSM4T(r, a) \
    asm volatile("ldmatrix.sync.aligned.m8n8.x4.trans.shared.b16 {%0,%1,%2,%3}, [%4];" \
        : "=r"((r)[0]), "=r"((r)[1]), "=r"((r)[2]), "=r"((r)[3]) : "r"(a))
#define MMA_F16(c, a, b) \
    asm volatile("mma.sync.aligned.m16n8k16.row.col.f32.f16.f16.f32 " \
        "{%0,%1,%2,%3}, {%4,%5,%6,%7}, {%8,%9}, {%0,%1,%2,%3};" \
        : "+f"((c)[0]), "+f"((c)[1]), "+f"((c)[2]), "+f"((c)[3]) \
        : "r"((a)[0]), "r"((a)[1]), "r"((a)[2]), "r"((a)[3]), "r"((b)[0]), "r"((b)[1]))
#define CP_ASYNC16(d, g) \
    asm volatile("cp.async.cg.shared.global [%0], [%1], 16;" :: "r"(d), "l"(g))
#define CP_COMMIT() asm volatile("cp.async.commit_group;" ::: "memory")
#define CP_WAIT0()  asm volatile("cp.async.wait_group 0;" ::: "memory")
#define CP_WAIT1()  asm volatile("cp.async.wait_group 1;" ::: "memory")

__device__ __forceinline__ uint32_t pack_h2(float a, float b) {
    __half2 h; h.x = __float2half_rn(a); h.y = __float2half_rn(b);
    return *(uint32_t*)&h;
}

// ---------------- embedding ---------------------------------------------------
__global__ void embed_k(const int* __restrict__ idx,
                        const float* __restrict__ tok,
                        const float* __restrict__ pos) {
    int m = blockIdx.x;
    int t = m & (T_ - 1);
    const float* te = tok + (size_t)idx[m] * D_;
    const float* pe = pos + (size_t)t * D_;
    float* xr = g_x + (size_t)m * D_;
    for (int d = threadIdx.x; d < D_; d += blockDim.x)
        xr[d] = te[d] + pe[d];
}

// ---------------- weight convert: fp32 -> fp16 (elementwise) ------------------
__global__ void convw1(const float* __restrict__ W, __half* __restrict__ hi) {
    size_t idx = ((size_t)blockIdx.x * 256 + threadIdx.x) * 8;
    float4 v0 = *(const float4*)(W + idx);
    float4 v1 = *(const float4*)(W + idx + 4);
    union { uint4 u; __half b[8]; } ph;
    ph.b[0] = __float2half_rn(v0.x); ph.b[1] = __float2half_rn(v0.y);
    ph.b[2] = __float2half_rn(v0.z); ph.b[3] = __float2half_rn(v0.w);
    ph.b[4] = __float2half_rn(v1.x); ph.b[5] = __float2half_rn(v1.y);
    ph.b[6] = __float2half_rn(v1.z); ph.b[7] = __float2half_rn(v1.w);
    *(uint4*)(hi + idx) = ph.u;
}

// qw/kw/vw are [L][D][D]; dest wqkv [L][D][3D]
__global__ void convqkv(const float* __restrict__ W, int colOff,
                        __half* __restrict__ hi) {
    long z = blockIdx.y;
    long idx = ((long)blockIdx.x * 256 + threadIdx.x) * 4;
    int k = (int)(idx >> 10);
    int n = (int)(idx & 1023);
    float4 v = *(const float4*)(W + z * (1 << 20) + idx);
    size_t d = (size_t)z * (3 << 20) + (size_t)k * (3 * D_) + colOff + n;
    union { uint2 u; __half b[4]; } ph;
    ph.b[0] = __float2half_rn(v.x); ph.b[1] = __float2half_rn(v.y);
    ph.b[2] = __float2half_rn(v.z); ph.b[3] = __float2half_rn(v.w);
    *(uint2*)(hi + d) = ph.u;
}

// ---------------- layernorm: writes single fp16 (and/or fp32) -----------------
__global__ void ln_k(const float* __restrict__ in, long in_stride,
                     const float* __restrict__ w, const float* __restrict__ b,
                     __half* __restrict__ oh, float* __restrict__ of) {
    const float* row = in + (size_t)blockIdx.x * in_stride;
    int tid = threadIdx.x;
    float vals[4];
    float s = 0.f;
    #pragma unroll
    for (int i = 0; i < 4; i++) { vals[i] = row[tid + 256 * i]; s += vals[i]; }

    __shared__ float red[8];
    int lane = tid & 31, warp = tid >> 5;
    #pragma unroll
    for (int off = 16; off; off >>= 1) s += __shfl_xor_sync(0xffffffffu, s, off);
    if (lane == 0) red[warp] = s;
    __syncthreads();
    float tot = 0.f;
    #pragma unroll
    for (int i = 0; i < 8; i++) tot += red[i];
    float mean = tot * (1.0f / D_);

    float s2 = 0.f;
    #pragma unroll
    for (int i = 0; i < 4; i++) { float d = vals[i] - mean; s2 += d * d; }
    __syncthreads();
    #pragma unroll
    for (int off = 16; off; off >>= 1) s2 += __shfl_xor_sync(0xffffffffu, s2, off);
    if (lane == 0) red[warp] = s2;
    __syncthreads();
    float tot2 = 0.f;
    #pragma unroll
    for (int i = 0; i < 8; i++) tot2 += red[i];
    float inv = rsqrtf(tot2 * (1.0f / D_) + 1e-5f);

    size_t base = (size_t)blockIdx.x * D_;
    #pragma unroll
    for (int i = 0; i < 4; i++) {
        int d = tid + 256 * i;
        float v = (vals[i] - mean) * inv * w[d] + b[d];
        if (of) of[base + d] = v;
        if (oh) oh[base + d] = __float2half_rn(v);
    }
}

// ---------------- mma.sync fp16 GEMM (single pass), 128x128x32, 3-stage -------
// A: [M,K] row-major fp16. B: [K,N] row-major fp16.
// MODE 0: QKV: split/permute into q/k/v (K transposed layout); q pre-scaled
// MODE 1: fp32 out = acc + bias0 + res
// MODE 2: fp16 out = relu(acc + bias0)
#define A_TILE   10240                       // 128 rows x 80B
#define B_TILE   8704                        // 32 rows x 272B
#define STAGE_B  (A_TILE + B_TILE)           // 18944
#define GSMEM    (3 * STAGE_B)               // 56832

template<int MODE>
__global__ __launch_bounds__(256, 1)
void gemm_tc(const __half* __restrict__ A, const __half* __restrict__ Bw,
             const float* __restrict__ bias0, const float* __restrict__ bias1,
             const float* __restrict__ bias2, const float* __restrict__ res,
             float* __restrict__ Cf, __half* __restrict__ Ch,
             __half* p0, __half* p1, __half* p2,
             int Kdim, int Nb, int Nout) {
    extern __shared__ char smem[];
    const uint32_t sb = smem_u32(smem);
    const int tid = threadIdx.x, lane = tid & 31, wid = tid >> 5;
    const int bm = blockIdx.y * 128, bn = blockIdx.x * 128;
    const int wm = wid & 1, wn = wid >> 1;     // warp tile: 64 x 32

    const int KT = Kdim >> 5;

    auto load_stage = [&](int ss) {
        const uint32_t dst = sb + (ss % 3) * STAGE_B;
        const int kg = ss * 32;
        #pragma unroll
        for (int i = 0; i < 2; i++) {
            int ch = tid + 256 * i;            // 0..511
            int r = ch >> 2;
            const __half* ga = A + (size_t)(bm + r) * Kdim + kg + (ch & 3) * 8;
            CP_ASYNC16(dst + r * 80 + (ch & 3) * 16, ga);
        }
        #pragma unroll
        for (int i = 0; i < 2; i++) {
            int ch = tid + 256 * i;
            int r = ch >> 4, c = (ch & 15) * 8;
            const __half* gb = Bw + (size_t)(kg + r) * Nb + bn + c;
            CP_ASYNC16(dst + A_TILE + r * 272 + (ch & 15) * 16, gb);
        }
    };

    load_stage(0); CP_COMMIT();
    load_stage(1); CP_COMMIT();

    float acc[4][4][4] = {};

    for (int s = 0; s < KT; s++) {
        if (s == KT - 1) { CP_WAIT0(); } else { CP_WAIT1(); }
        __syncthreads();
        if (s + 2 < KT) { load_stage(s + 2); CP_COMMIT(); }

        const uint32_t base = sb + (s % 3) * STAGE_B;
        #pragma unroll
        for (int ks = 0; ks < 2; ks++) {
            uint32_t ah[4][4], bh[2][4];
            #pragma unroll
            for (int mi = 0; mi < 4; mi++) {
                uint32_t ra = base + (wm * 64 + mi * 16 + (lane & 15)) * 80
                            + ks * 32 + (lane >> 4) * 16;
                LDSM4(ah[mi], ra);
            }
            #pragma unroll
            for (int g = 0; g < 2; g++) {
                uint32_t rb = base + A_TILE + (ks * 16 + (lane & 15)) * 272
                            + (wn * 32 + g * 16) * 2 + (lane >> 4) * 16;
                LDSM4T(bh[g], rb);
            }
            #pragma unroll
            for (int mi = 0; mi < 4; mi++)
                #pragma unroll
                for (int ni = 0; ni < 4; ni++) {
                    const uint32_t* bhp = &bh[ni >> 1][(ni & 1) * 2];
                    MMA_F16(acc[mi][ni], ah[mi], bhp);
                }
        }
        __syncthreads();
    }

    // epilogue
    #pragma unroll
    for (int mi = 0; mi < 4; mi++) {
        const int r0 = bm + wm * 64 + mi * 16 + (lane >> 2);
        #pragma unroll
        for (int rr = 0; rr < 2; rr++) {
            const int m = r0 + rr * 8;
            const int bt = m >> 10, tt = m & (T_ - 1);
            #pragma unroll
            for (int ni = 0; ni < 4; ni++) {
                const int cc = bn + wn * 32 + ni * 8 + (lane & 3) * 2;
                float v0 = acc[mi][ni][rr * 2 + 0];
                float v1 = acc[mi][ni][rr * 2 + 1];
                if (MODE == 0) {
                    const int which = cc >> 10;
                    const int nn = cc & 1023;
                    const float* bp = (which == 0) ? bias0 : (which == 1 ? bias1 : bias2);
                    const int h = nn >> 6, hd = nn & 63;
                    const int bh_ = bt * H_ + h;
                    v0 += bp[nn]; v1 += bp[nn + 1];
                    if (which == 0) { v0 *= 0.125f; v1 *= 0.125f; }
                    __half h0 = __float2half_rn(v0), h1 = __float2half_rn(v1);
                    if (which == 1) {
                        // K transposed: [bh][hd][T]
                        size_t o0 = ((size_t)bh_ * HD_ + hd) * T_ + tt;
                        p1[o0] = h0; p1[o0 + T_] = h1;
                    } else {
                        size_t o = ((size_t)bh_ * T_ + tt) * HD_ + hd;
                        __half2 hh; hh.x = h0; hh.y = h1;
                        if (which == 0) *(__half2*)(p0 + o) = hh;
                        else            *(__half2*)(p2 + o) = hh;
                    }
                } else if (MODE == 1) {
                    size_t idx = (size_t)m * Nout + cc;
                    float2 bv = *(const float2*)(bias0 + cc);
                    float2 rv = *(const float2*)(res + idx);
                    float2 o2 = {v0 + bv.x + rv.x, v1 + bv.y + rv.y};
                    *(float2*)(Cf + idx) = o2;
                } else {
                    size_t idx = (size_t)m * Nout + cc;
                    float2 bv = *(const float2*)(bias0 + cc);
                    __half2 hh;
                    hh.x = __float2half_rn(fmaxf(v0 + bv.x, 0.f));
                    hh.y = __float2half_rn(fmaxf(v1 + bv.y, 0.f));
                    *(__half2*)(Ch + idx) = hh;
                }
            }
        }
    }
}

// ---------------- tensor-core flash attention (single fp16, 1-pass) -----------
// Grid (T/64, BH), 128 threads (4 warps; warp owns 16 query rows).
// Q [BH,T,HD] (pre-scaled), K [BH,HD,T], V [BH,T,HD]. Out fp16 [M,D].
#define APAD 72
#define ATILE_H (64 * APAD)          // halves per tile
#define ATT_SMEM (3 * ATILE_H * 2)   // 27648 bytes

__global__ __launch_bounds__(128)
void attn_k(const __half* __restrict__ qg, const __half* __restrict__ kg,
            const __half* __restrict__ vg, __half* __restrict__ oh) {
    extern __shared__ __half as_[];
    __half* Qs = as_;
    __half* Ks = Qs + ATILE_H;
    __half* Vs = Ks + ATILE_H;

    const int tid = threadIdx.x, lane = tid & 31, warp = tid >> 5;
    const int bh = blockIdx.y, q0 = blockIdx.x * 64;
    const int b = bh >> 4, h = bh & 15;

    // load Q tile (64 x 64 halves)
    #pragma unroll
    for (int i = 0; i < 4; i++) {
        int ch = tid + 128 * i;
        int r = ch >> 3, c = (ch & 7) * 8;
        *(uint4*)&Qs[r * APAD + c] =
            *(const uint4*)(qg + ((size_t)bh * T_ + q0 + r) * HD_ + c);
    }
    __syncthreads();

    // Q fragments
    uint32_t aq[4][4];
    const uint32_t qbase = smem_u32(Qs);
    #pragma unroll
    for (int kf = 0; kf < 4; kf++) {
        uint32_t ra = qbase + ((warp * 16 + (lane & 15)) * APAD + kf * 16 + (lane >> 4) * 8) * 2;
        LDSM4(aq[kf], ra);
    }

    float mx[2] = {-1e30f, -1e30f}, lsum[2] = {0.f, 0.f};
    float oacc[8][4] = {};

    const uint32_t kbase = smem_u32(Ks);
    const uint32_t vbase = smem_u32(Vs);
    const int ntiles = blockIdx.x + 1;

    for (int jt = 0; jt < ntiles; jt++) {
        const int j0 = jt * 64;
        __syncthreads();
        #pragma unroll
        for (int i = 0; i < 4; i++) {
            int ch = tid + 128 * i;
            int r = ch >> 3, c = (ch & 7) * 8;
            *(uint4*)&Ks[r * APAD + c] =
                *(const uint4*)(kg + ((size_t)bh * HD_ + r) * T_ + j0 + c);
            *(uint4*)&Vs[r * APAD + c] =
                *(const uint4*)(vg + ((size_t)bh * T_ + j0 + r) * HD_ + c);
        }
        __syncthreads();

        // scores: S = Q . K^T
        float sacc[8][4] = {};
        #pragma unroll
        for (int kf = 0; kf < 4; kf++) {
            #pragma unroll
            for (int g = 0; g < 4; g++) {
                uint32_t kb2[4];
                uint32_t rb = kbase + ((kf * 16 + (lane & 15)) * APAD + g * 16 + (lane >> 4) * 8) * 2;
                LDSM4T(kb2, rb);
                MMA_F16(sacc[2 * g],     aq[kf], kb2);
                MMA_F16(sacc[2 * g + 1], aq[kf], kb2 + 2);
            }
        }

        // causal mask on diagonal tile
        if (jt == blockIdx.x) {
            const int rbase = q0 + warp * 16 + (lane >> 2);
            #pragma unroll
            for (int nf = 0; nf < 8; nf++) {
                int c0 = j0 + nf * 8 + (lane & 3) * 2;
                if (c0     > rbase)     sacc[nf][0] = -1e30f;
                if (c0 + 1 > rbase)     sacc[nf][1] = -1e30f;
                if (c0     > rbase + 8) sacc[nf][2] = -1e30f;
                if (c0 + 1 > rbase + 8) sacc[nf][3] = -1e30f;
            }
        }

        // online softmax per row-half
        #pragma unroll
        for (int hf = 0; hf < 2; hf++) {
            float mnew = -1e30f;
            #pragma unroll
            for (int nf = 0; nf < 8; nf++)
                mnew = fmaxf(mnew, fmaxf(sacc[nf][hf * 2], sacc[nf][hf * 2 + 1]));
            mnew = fmaxf(mnew, __shfl_xor_sync(0xffffffffu, mnew, 1));
            mnew = fmaxf(mnew, __shfl_xor_sync(0xffffffffu, mnew, 2));
            float mn = fmaxf(mx[hf], mnew);
            float corr = __expf(mx[hf] - mn);
            float ps = 0.f;
            #pragma unroll
            for (int nf = 0; nf < 8; nf++) {
                float s0 = __expf(sacc[nf][hf * 2]     - mn);
                float s1 = __expf(sacc[nf][hf * 2 + 1] - mn);
                sacc[nf][hf * 2] = s0; sacc[nf][hf * 2 + 1] = s1;
                ps += s0 + s1;
            }
            ps += __shfl_xor_sync(0xffffffffu, ps, 1);
            ps += __shfl_xor_sync(0xffffffffu, ps, 2);
            lsum[hf] = lsum[hf] * corr + ps;
            #pragma unroll
            for (int nf = 0; nf < 8; nf++) {
                oacc[nf][hf * 2] *= corr; oacc[nf][hf * 2 + 1] *= corr;
            }
            mx[hf] = mn;
        }

        // pack P into fp16 A-fragments
        uint32_t pah[4][4];
        #pragma unroll
        for (int kf = 0; kf < 4; kf++) {
            const float* s0 = sacc[2 * kf];
            const float* s1 = sacc[2 * kf + 1];
            pah[kf][0] = pack_h2(s0[0], s0[1]);
            pah[kf][1] = pack_h2(s0[2], s0[3]);
            pah[kf][2] = pack_h2(s1[0], s1[1]);
            pah[kf][3] = pack_h2(s1[2], s1[3]);
        }

        // O += P . V
        #pragma unroll
        for (int kf = 0; kf < 4; kf++) {
            #pragma unroll
            for (int g = 0; g < 4; g++) {
                uint32_t vb2[4];
                uint32_t rb = vbase + ((kf * 16 + (lane & 15)) * APAD + g * 16 + (lane >> 4) * 8) * 2;
                LDSM4T(vb2, rb);
                MMA_F16(oacc[2 * g],     pah[kf], vb2);
                MMA_F16(oacc[2 * g + 1], pah[kf], vb2 + 2);
            }
        }
    }

    // epilogue: normalize and store fp16 to [M, D]
    #pragma unroll
    for (int hf = 0; hf < 2; hf++) {
        float inv = 1.0f / lsum[hf];
        int row = q0 + warp * 16 + (lane >> 2) + hf * 8;
        size_t rbase = ((size_t)(b * T_ + row)) * D_ + h * HD_;
        #pragma unroll
        for (int nf = 0; nf < 8; nf++) {
            int col = nf * 8 + (lane & 3) * 2;
            __half2 o2;
            o2.x = __float2half_rn(oacc[nf][hf * 2]     * inv);
            o2.y = __float2half_rn(oacc[nf][hf * 2 + 1] * inv);
            *(__half2*)(oh + rbase + col) = o2;
        }
    }
}

// ---------------- head GEMV ----------------------------------------------------
__global__ __launch_bounds__(256)
void head_k(const float* __restrict__ hf, const float* __restrict__ W,
            const float* __restrict__ hb, float* __restrict__ out) {
    __shared__ float s0[D_];
    __shared__ float s1[D_];
    for (int i = threadIdx.x; i < D_; i += 256) { s0[i] = hf[i]; s1[i] = hf[D_ + i]; }
    __syncthreads();
    int vcol = blockIdx.x * 256 + threadIdx.x;
    float a0 = 0.f, a1 = 0.f;
    #pragma unroll 4
    for (int d = 0; d < D_; d++) {
        float wv = W[(size_t)d * V_ + vcol];
        a0 += s0[d] * wv;
        a1 += s1[d] * wv;
    }
    float bb = hb[vcol];
    out[vcol]      = a0 + bb;
    out[V_ + vcol] = a1 + bb;
}

// ---------------- launch --------------------------------------------------
extern "C" void kernel_launch(void* const* d_in, const int* in_sizes, int n_in,
                              void* d_out, int out_size) {
    const int*   idx    = (const int*)  d_in[0];
    const float* tok    = (const float*)d_in[1];
    const float* pos    = (const float*)d_in[2];
    const float* ln1w   = (const float*)d_in[3];
    const float* ln1b   = (const float*)d_in[4];
    const float* qw     = (const float*)d_in[5];
    const float* qb     = (const float*)d_in[6];
    const float* kw     = (const float*)d_in[7];
    const float* kbi    = (const float*)d_in[8];
    const float* vw     = (const float*)d_in[9];
    const float* vb     = (const float*)d_in[10];
    const float* ow     = (const float*)d_in[11];
    const float* ob     = (const float*)d_in[12];
    const float* ln2w   = (const float*)d_in[13];
    const float* ln2b   = (const float*)d_in[14];
    const float* f1w    = (const float*)d_in[15];
    const float* f1b    = (const float*)d_in[16];
    const float* f2w    = (const float*)d_in[17];
    const float* f2b    = (const float*)d_in[18];
    const float* lnfw   = (const float*)d_in[19];
    const float* lnfb   = (const float*)d_in[20];
    const float* headw  = (const float*)d_in[21];
    const float* headb  = (const float*)d_in[22];

    float *x, *hf;
    __half *wqkv, *wo, *wf1, *wf2, *q, *k, *v, *hh, *oh, *ffh;
    cudaGetSymbolAddress((void**)&x,    g_x);
    cudaGetSymbolAddress((void**)&hf,   g_hf);
    cudaGetSymbolAddress((void**)&wqkv, g_wqkv);
    cudaGetSymbolAddress((void**)&wo,   g_wo);
    cudaGetSymbolAddress((void**)&wf1,  g_wf1);
    cudaGetSymbolAddress((void**)&wf2,  g_wf2);
    cudaGetSymbolAddress((void**)&q,    g_q);
    cudaGetSymbolAddress((void**)&k,    g_k);
    cudaGetSymbolAddress((void**)&v,    g_v);
    cudaGetSymbolAddress((void**)&hh,   g_hh);
    cudaGetSymbolAddress((void**)&oh,   g_oh);
    cudaGetSymbolAddress((void**)&ffh,  g_ffh);

    cudaFuncSetAttribute(gemm_tc<0>, cudaFuncAttributeMaxDynamicSharedMemorySize, GSMEM);
    cudaFuncSetAttribute(gemm_tc<1>, cudaFuncAttributeMaxDynamicSharedMemorySize, GSMEM);
    cudaFuncSetAttribute(gemm_tc<2>, cudaFuncAttributeMaxDynamicSharedMemorySize, GSMEM);
    cudaFuncSetAttribute(attn_k, cudaFuncAttributeMaxDynamicSharedMemorySize, ATT_SMEM);

    const long MEG = 1024 * 1024;
    dim3 gQKV(24, 16), gDD(8, 16), gF1(32, 16);
    dim3 gAt(T_ / 64, B_ * H_);

    embed_k<<<M_, 256>>>(idx, tok, pos);
    convqkv<<<dim3(1024, L_), 256>>>(qw, 0,    wqkv);
    convqkv<<<dim3(1024, L_), 256>>>(kw, 1024, wqkv);
    convqkv<<<dim3(1024, L_), 256>>>(vw, 2048, wqkv);
    ln_k<<<M_, 256>>>(x, D_, ln1w, ln1b, hh, nullptr);
    gemm_tc<0><<<gQKV, 256, GSMEM>>>(hh, wqkv, qb, kbi, vb, nullptr,
                                     nullptr, nullptr, q, k, v, D_, 3 * D_, 0);
    convw1<<<(L_ * MEG) / 2048, 256>>>(ow,  wo);
    convw1<<<(L_ * 4 * MEG) / 2048, 256>>>(f1w, wf1);
    convw1<<<(L_ * 4 * MEG) / 2048, 256>>>(f2w, wf2);

    for (int l = 0; l < L_; l++) {
        size_t wq3 = (size_t)l * 3 * MEG;
        size_t wdd = (size_t)l * MEG;
        size_t wff = (size_t)l * 4 * MEG;

        if (l > 0) {
            ln_k<<<M_, 256>>>(x, D_, ln1w + l * D_, ln1b + l * D_, hh, nullptr);
            gemm_tc<0><<<gQKV, 256, GSMEM>>>(hh, wqkv + wq3,
                                             qb + l * D_, kbi + l * D_, vb + l * D_,
                                             nullptr, nullptr, nullptr,
                                             q, k, v, D_, 3 * D_, 0);
        }

        attn_k<<<gAt, 128, ATT_SMEM>>>(q, k, v, oh);

        gemm_tc<1><<<gDD, 256, GSMEM>>>(oh, wo + wdd,
                                        ob + l * D_, nullptr, nullptr, x,
                                        x, nullptr, nullptr, nullptr, nullptr,
                                        D_, D_, D_);

        ln_k<<<M_, 256>>>(x, D_, ln2w + l * D_, ln2b + l * D_, hh, nullptr);

        gemm_tc<2><<<gF1, 256, GSMEM>>>(hh, wf1 + wff,
                                        f1b + l * FF_, nullptr, nullptr, nullptr,
                                        nullptr, ffh, nullptr, nullptr, nullptr,
                                        D_, FF_, FF_);

        gemm_tc<1><<<gDD, 256, GSMEM>>>(ffh, wf2 + wff,
                                        f2b + l * D_, nullptr, nullptr, x,
                                        x, nullptr, nullptr, nullptr, nullptr,
                                        FF_, D_, D_);
    }

    ln_k<<<B_, 256>>>(x + (size_t)(T_ - 1) * D_, (long)T_ * D_, lnfw, lnfb,
                      nullptr, hf);

    head_k<<<V_ / 256, 256>>>(hf, headw, headb, (float*)d_out);
}

// round 8
// speedup vs baseline: 9.2968x; 1.2112x over previous
#include <cuda_runtime.h>
#include <cuda_fp16.h>
#include <cstdint>

#define D_  1024
#define H_  16
#define HD_ 64
#define T_  1024
#define B_  2
#define L_  8
#define FF_ 4096
#define V_  32000
#define M_  (B_ * T_)   // 2048 rows

// ---------------- scratch (device globals) ----------------------------------
__device__ __half g_wqkv[(size_t)L_ * D_ * 3 * D_];
__device__ __half g_wo  [(size_t)L_ * D_ * D_];
__device__ __half g_wf1 [(size_t)L_ * D_ * FF_];
__device__ __half g_wf2 [(size_t)L_ * FF_ * D_];
__device__ float g_x [M_ * D_];
__device__ __half g_q[M_ * D_];
__device__ __half g_k[M_ * D_];   // transposed [BH][HD][T]
__device__ __half g_v[M_ * D_];
__device__ __half g_hh [M_ * D_];
__device__ __half g_oh [M_ * D_];
__device__ __half g_ffh[M_ * FF_];
__device__ float g_hf[B_ * D_];

// ---------------- ptx helpers ------------------------------------------------
__device__ __forceinline__ uint32_t smem_u32(const void* p) {
    uint32_t a;
    asm("{ .reg .u64 t; cvta.to.shared.u64 t, %1; cvt.u32.u64 %0, t; }" : "=r"(a) : "l"(p));
    return a;
}
#define LDSM4(r, a) \
    asm volatile("ldmatrix.sync.aligned.m8n8.x4.shared.b16 {%0,%1,%2,%3}, [%4];" \
        : "=r"((r)[0]), "=r"((r)[1]), "=r"((r)[2]), "=r"((r)[3]) : "r"(a))
#define LDSM4T(r, a) \
    asm volatile("ldmatrix.sync.aligned.m8n8.x4.trans.shared.b16 {%0,%1,%2,%3}, [%4];" \
        : "=r"((r)[0]), "=r"((r)[1]), "=r"((r)[2]), "=r"((r)[3]) : "r"(a))
#define MMA_F16(c, a, b) \
    asm volatile("mma.sync.aligned.m16n8k16.row.col.f32.f16.f16.f32 " \
        "{%0,%1,%2,%3}, {%4,%5,%6,%7}, {%8,%9}, {%0,%1,%2,%3};" \
        : "+f"((c)[0]), "+f"((c)[1]), "+f"((c)[2]), "+f"((c)[3]) \
        : "r"((a)[0]), "r"((a)[1]), "r"((a)[2]), "r"((a)[3]), "r"((b)[0]), "r"((b)[1]))
#define CP_ASYNC16(d, g) \
    asm volatile("cp.async.cg.shared.global [%0], [%1], 16;" :: "r"(d), "l"(g))
#define CP_COMMIT() asm volatile("cp.async.commit_group;" ::: "memory")
#define CP_WAIT0()  asm volatile("cp.async.wait_group 0;" ::: "memory")
#define CP_WAIT1()  asm volatile("cp.async.wait_group 1;" ::: "memory")

__device__ __forceinline__ uint32_t pack_h2(float a, float b) {
    __half2 h; h.x = __float2half_rn(a); h.y = __float2half_rn(b);
    return *(uint32_t*)&h;
}

// ---------------- embedding ---------------------------------------------------
__global__ void embed_k(const int* __restrict__ idx,
                        const float* __restrict__ tok,
                        const float* __restrict__ pos) {
    int m = blockIdx.x;
    int t = m & (T_ - 1);
    const float* te = tok + (size_t)idx[m] * D_;
    const float* pe = pos + (size_t)t * D_;
    float* xr = g_x + (size_t)m * D_;
    for (int d = threadIdx.x; d < D_; d += blockDim.x)
        xr[d] = te[d] + pe[d];
}

// ---------------- weight convert ----------------------------------------------
__global__ void convw1(const float* __restrict__ W, __half* __restrict__ hi) {
    size_t idx = ((size_t)blockIdx.x * 256 + threadIdx.x) * 8;
    float4 v0 = *(const float4*)(W + idx);
    float4 v1 = *(const float4*)(W + idx + 4);
    union { uint4 u; __half b[8]; } ph;
    ph.b[0] = __float2half_rn(v0.x); ph.b[1] = __float2half_rn(v0.y);
    ph.b[2] = __float2half_rn(v0.z); ph.b[3] = __float2half_rn(v0.w);
    ph.b[4] = __float2half_rn(v1.x); ph.b[5] = __float2half_rn(v1.y);
    ph.b[6] = __float2half_rn(v1.z); ph.b[7] = __float2half_rn(v1.w);
    *(uint4*)(hi + idx) = ph.u;
}

__global__ void convqkv(const float* __restrict__ W, int colOff,
                        __half* __restrict__ hi) {
    long z = blockIdx.y;
    long idx = ((long)blockIdx.x * 256 + threadIdx.x) * 4;
    int k = (int)(idx >> 10);
    int n = (int)(idx & 1023);
    float4 v = *(const float4*)(W + z * (1 << 20) + idx);
    size_t d = (size_t)z * (3 << 20) + (size_t)k * (3 * D_) + colOff + n;
    union { uint2 u; __half b[4]; } ph;
    ph.b[0] = __float2half_rn(v.x); ph.b[1] = __float2half_rn(v.y);
    ph.b[2] = __float2half_rn(v.z); ph.b[3] = __float2half_rn(v.w);
    *(uint2*)(hi + d) = ph.u;
}

// ---------------- layernorm ----------------------------------------------------
__global__ void ln_k(const float* __restrict__ in, long in_stride,
                     const float* __restrict__ w, const float* __restrict__ b,
                     __half* __restrict__ oh, float* __restrict__ of) {
    const float* row = in + (size_t)blockIdx.x * in_stride;
    int tid = threadIdx.x;
    float vals[4];
    float s = 0.f;
    #pragma unroll
    for (int i = 0; i < 4; i++) { vals[i] = row[tid + 256 * i]; s += vals[i]; }

    __shared__ float red[8];
    int lane = tid & 31, warp = tid >> 5;
    #pragma unroll
    for (int off = 16; off; off >>= 1) s += __shfl_xor_sync(0xffffffffu, s, off);
    if (lane == 0) red[warp] = s;
    __syncthreads();
    float tot = 0.f;
    #pragma unroll
    for (int i = 0; i < 8; i++) tot += red[i];
    float mean = tot * (1.0f / D_);

    float s2 = 0.f;
    #pragma unroll
    for (int i = 0; i < 4; i++) { float d = vals[i] - mean; s2 += d * d; }
    __syncthreads();
    #pragma unroll
    for (int off = 16; off; off >>= 1) s2 += __shfl_xor_sync(0xffffffffu, s2, off);
    if (lane == 0) red[warp] = s2;
    __syncthreads();
    float tot2 = 0.f;
    #pragma unroll
    for (int i = 0; i < 8; i++) tot2 += red[i];
    float inv = rsqrtf(tot2 * (1.0f / D_) + 1e-5f);

    size_t base = (size_t)blockIdx.x * D_;
    #pragma unroll
    for (int i = 0; i < 4; i++) {
        int d = tid + 256 * i;
        float v = (vals[i] - mean) * inv * w[d] + b[d];
        if (of) of[base + d] = v;
        if (oh) oh[base + d] = __float2half_rn(v);
    }
}

// ---------------- mma.sync fp16 GEMM, BMx128x32, 3-stage, 2 CTA/SM -------------
// A: [M,K] row-major fp16. B: [K,N] row-major fp16.
// MODE 0: QKV split/permute (q pre-scaled, k transposed); 1: +bias+res fp32;
// MODE 2: relu fp16.
#define B_TILE 8704                         // 32 rows x 272B

template<int MODE, int BM>
__global__ __launch_bounds__(256, 2)
void gemm_tc(const __half* __restrict__ A, const __half* __restrict__ Bw,
             const float* __restrict__ bias0, const float* __restrict__ bias1,
             const float* __restrict__ bias2, const float* __restrict__ res,
             float* __restrict__ Cf, __half* __restrict__ Ch,
             __half* p0, __half* p1, __half* p2,
             int Kdim, int Nb, int Nout) {
    constexpr int MI     = BM / 32;          // m-frags per warp
    constexpr int A_TILE = BM * 80;
    constexpr int STAGE  = A_TILE + B_TILE;

    extern __shared__ char smem[];
    const uint32_t sb = smem_u32(smem);
    const int tid = threadIdx.x, lane = tid & 31, wid = tid >> 5;
    const int bm = blockIdx.y * BM, bn = blockIdx.x * 128;
    const int wm = wid & 1, wn = wid >> 1;   // warp tile: (BM/2) x 32

    const int KT = Kdim >> 5;

    auto load_stage = [&](int ss) {
        const uint32_t dst = sb + (ss % 3) * STAGE;
        const int kg = ss * 32;
        #pragma unroll
        for (int i = 0; i < BM / 64; i++) {
            int ch = tid + 256 * i;
            int r = ch >> 2;
            const __half* ga = A + (size_t)(bm + r) * Kdim + kg + (ch & 3) * 8;
            CP_ASYNC16(dst + r * 80 + (ch & 3) * 16, ga);
        }
        #pragma unroll
        for (int i = 0; i < 2; i++) {
            int ch = tid + 256 * i;
            int r = ch >> 4, c = (ch & 15) * 8;
            const __half* gb = Bw + (size_t)(kg + r) * Nb + bn + c;
            CP_ASYNC16(dst + A_TILE + r * 272 + (ch & 15) * 16, gb);
        }
    };

    load_stage(0); CP_COMMIT();
    load_stage(1); CP_COMMIT();

    float acc[MI][4][4] = {};

    for (int s = 0; s < KT; s++) {
        if (s == KT - 1) { CP_WAIT0(); } else { CP_WAIT1(); }
        __syncthreads();
        if (s + 2 < KT) { load_stage(s + 2); CP_COMMIT(); }

        const uint32_t base = sb + (s % 3) * STAGE;
        #pragma unroll
        for (int ks = 0; ks < 2; ks++) {
            uint32_t ah[MI][4], bh[2][4];
            #pragma unroll
            for (int mi = 0; mi < MI; mi++) {
                uint32_t ra = base + (wm * (BM / 2) + mi * 16 + (lane & 15)) * 80
                            + ks * 32 + (lane >> 4) * 16;
                LDSM4(ah[mi], ra);
            }
            #pragma unroll
            for (int g = 0; g < 2; g++) {
                uint32_t rb = base + A_TILE + (ks * 16 + (lane & 15)) * 272
                            + (wn * 32 + g * 16) * 2 + (lane >> 4) * 16;
                LDSM4T(bh[g], rb);
            }
            #pragma unroll
            for (int mi = 0; mi < MI; mi++)
                #pragma unroll
                for (int ni = 0; ni < 4; ni++) {
                    const uint32_t* bhp = &bh[ni >> 1][(ni & 1) * 2];
                    MMA_F16(acc[mi][ni], ah[mi], bhp);
                }
        }
    }

    // epilogue
    #pragma unroll
    for (int mi = 0; mi < MI; mi++) {
        const int r0 = bm + wm * (BM / 2) + mi * 16 + (lane >> 2);
        #pragma unroll
        for (int rr = 0; rr < 2; rr++) {
            const int m = r0 + rr * 8;
            const int bt = m >> 10, tt = m & (T_ - 1);
            #pragma unroll
            for (int ni = 0; ni < 4; ni++) {
                const int cc = bn + wn * 32 + ni * 8 + (lane & 3) * 2;
                float v0 = acc[mi][ni][rr * 2 + 0];
                float v1 = acc[mi][ni][rr * 2 + 1];
                if (MODE == 0) {
                    const int which = cc >> 10;
                    const int nn = cc & 1023;
                    const float* bp = (which == 0) ? bias0 : (which == 1 ? bias1 : bias2);
                    const int h = nn >> 6, hd = nn & 63;
                    const int bh_ = bt * H_ + h;
                    v0 += bp[nn]; v1 += bp[nn + 1];
                    if (which == 0) { v0 *= 0.125f; v1 *= 0.125f; }
                    __half h0 = __float2half_rn(v0), h1 = __float2half_rn(v1);
                    if (which == 1) {
                        size_t o0 = ((size_t)bh_ * HD_ + hd) * T_ + tt;
                        p1[o0] = h0; p1[o0 + T_] = h1;
                    } else {
                        size_t o = ((size_t)bh_ * T_ + tt) * HD_ + hd;
                        __half2 hh; hh.x = h0; hh.y = h1;
                        if (which == 0) *(__half2*)(p0 + o) = hh;
                        else            *(__half2*)(p2 + o) = hh;
                    }
                } else if (MODE == 1) {
                    size_t idx = (size_t)m * Nout + cc;
                    float2 bv = *(const float2*)(bias0 + cc);
                    float2 rv = *(const float2*)(res + idx);
                    float2 o2 = {v0 + bv.x + rv.x, v1 + bv.y + rv.y};
                    *(float2*)(Cf + idx) = o2;
                } else {
                    size_t idx = (size_t)m * Nout + cc;
                    float2 bv = *(const float2*)(bias0 + cc);
                    __half2 hh;
                    hh.x = __float2half_rn(fmaxf(v0 + bv.x, 0.f));
                    hh.y = __float2half_rn(fmaxf(v1 + bv.y, 0.f));
                    *(__half2*)(Ch + idx) = hh;
                }
            }
        }
    }
}

// ---------------- tensor-core flash attention ----------------------------------
#define APAD 72
#define ATILE_H (64 * APAD)
#define ATT_SMEM (3 * ATILE_H * 2)   // 27648 bytes

__global__ __launch_bounds__(128)
void attn_k(const __half* __restrict__ qg, const __half* __restrict__ kg,
            const __half* __restrict__ vg, __half* __restrict__ oh) {
    extern __shared__ __half as_[];
    __half* Qs = as_;
    __half* Ks = Qs + ATILE_H;
    __half* Vs = Ks + ATILE_H;

    const int tid = threadIdx.x, lane = tid & 31, warp = tid >> 5;
    const int bh = blockIdx.y, q0 = blockIdx.x * 64;
    const int b = bh >> 4, h = bh & 15;

    #pragma unroll
    for (int i = 0; i < 4; i++) {
        int ch = tid + 128 * i;
        int r = ch >> 3, c = (ch & 7) * 8;
        *(uint4*)&Qs[r * APAD + c] =
            *(const uint4*)(qg + ((size_t)bh * T_ + q0 + r) * HD_ + c);
    }
    __syncthreads();

    uint32_t aq[4][4];
    const uint32_t qbase = smem_u32(Qs);
    #pragma unroll
    for (int kf = 0; kf < 4; kf++) {
        uint32_t ra = qbase + ((warp * 16 + (lane & 15)) * APAD + kf * 16 + (lane >> 4) * 8) * 2;
        LDSM4(aq[kf], ra);
    }

    float mx[2] = {-1e30f, -1e30f}, lsum[2] = {0.f, 0.f};
    float oacc[8][4] = {};

    const uint32_t kbase = smem_u32(Ks);
    const uint32_t vbase = smem_u32(Vs);
    const int ntiles = blockIdx.x + 1;

    for (int jt = 0; jt < ntiles; jt++) {
        const int j0 = jt * 64;
        __syncthreads();
        #pragma unroll
        for (int i = 0; i < 4; i++) {
            int ch = tid + 128 * i;
            int r = ch >> 3, c = (ch & 7) * 8;
            *(uint4*)&Ks[r * APAD + c] =
                *(const uint4*)(kg + ((size_t)bh * HD_ + r) * T_ + j0 + c);
            *(uint4*)&Vs[r * APAD + c] =
                *(const uint4*)(vg + ((size_t)bh * T_ + j0 + r) * HD_ + c);
        }
        __syncthreads();

        float sacc[8][4] = {};
        #pragma unroll
        for (int kf = 0; kf < 4; kf++) {
            #pragma unroll
            for (int g = 0; g < 4; g++) {
                uint32_t kb2[4];
                uint32_t rb = kbase + ((kf * 16 + (lane & 15)) * APAD + g * 16 + (lane >> 4) * 8) * 2;
                LDSM4T(kb2, rb);
                MMA_F16(sacc[2 * g],     aq[kf], kb2);
                MMA_F16(sacc[2 * g + 1], aq[kf], kb2 + 2);
            }
        }

        if (jt == blockIdx.x) {
            const int rbase = q0 + warp * 16 + (lane >> 2);
            #pragma unroll
            for (int nf = 0; nf < 8; nf++) {
                int c0 = j0 + nf * 8 + (lane & 3) * 2;
                if (c0     > rbase)     sacc[nf][0] = -1e30f;
                if (c0 + 1 > rbase)     sacc[nf][1] = -1e30f;
                if (c0     > rbase + 8) sacc[nf][2] = -1e30f;
                if (c0 + 1 > rbase + 8) sacc[nf][3] = -1e30f;
            }
        }

        #pragma unroll
        for (int hf = 0; hf < 2; hf++) {
            float mnew = -1e30f;
            #pragma unroll
            for (int nf = 0; nf < 8; nf++)
                mnew = fmaxf(mnew, fmaxf(sacc[nf][hf * 2], sacc[nf][hf * 2 + 1]));
            mnew = fmaxf(mnew, __shfl_xor_sync(0xffffffffu, mnew, 1));
            mnew = fmaxf(mnew, __shfl_xor_sync(0xffffffffu, mnew, 2));
            float mn = fmaxf(mx[hf], mnew);
            float corr = __expf(mx[hf] - mn);
            float ps = 0.f;
            #pragma unroll
            for (int nf = 0; nf < 8; nf++) {
                float s0 = __expf(sacc[nf][hf * 2]     - mn);
                float s1 = __expf(sacc[nf][hf * 2 + 1] - mn);
                sacc[nf][hf * 2] = s0; sacc[nf][hf * 2 + 1] = s1;
                ps += s0 + s1;
            }
            ps += __shfl_xor_sync(0xffffffffu, ps, 1);
            ps += __shfl_xor_sync(0xffffffffu, ps, 2);
            lsum[hf] = lsum[hf] * corr + ps;
            #pragma unroll
            for (int nf = 0; nf < 8; nf++) {
                oacc[nf][hf * 2] *= corr; oacc[nf][hf * 2 + 1] *= corr;
            }
            mx[hf] = mn;
        }

        uint32_t pah[4][4];
        #pragma unroll
        for (int kf = 0; kf < 4; kf++) {
            const float* s0 = sacc[2 * kf];
            const float* s1 = sacc[2 * kf + 1];
            pah[kf][0] = pack_h2(s0[0], s0[1]);
            pah[kf][1] = pack_h2(s0[2], s0[3]);
            pah[kf][2] = pack_h2(s1[0], s1[1]);
            pah[kf][3] = pack_h2(s1[2], s1[3]);
        }

        #pragma unroll
        for (int kf = 0; kf < 4; kf++) {
            #pragma unroll
            for (int g = 0; g < 4; g++) {
                uint32_t vb2[4];
                uint32_t rb = vbase + ((kf * 16 + (lane & 15)) * APAD + g * 16 + (lane >> 4) * 8) * 2;
                LDSM4T(vb2, rb);
                MMA_F16(oacc[2 * g],     pah[kf], vb2);
                MMA_F16(oacc[2 * g + 1], pah[kf], vb2 + 2);
            }
        }
    }

    #pragma unroll
    for (int hf = 0; hf < 2; hf++) {
        float inv = 1.0f / lsum[hf];
        int row = q0 + warp * 16 + (lane >> 2) + hf * 8;
        size_t rbase = ((size_t)(b * T_ + row)) * D_ + h * HD_;
        #pragma unroll
        for (int nf = 0; nf < 8; nf++) {
            int col = nf * 8 + (lane & 3) * 2;
            __half2 o2;
            o2.x = __float2half_rn(oacc[nf][hf * 2]     * inv);
            o2.y = __float2half_rn(oacc[nf][hf * 2 + 1] * inv);
            *(__half2*)(oh + rbase + col) = o2;
        }
    }
}

// ---------------- head GEMV ------------------------------------------------------
__global__ __launch_bounds__(256)
void head_k(const float* __restrict__ hf, const float* __restrict__ W,
            const float* __restrict__ hb, float* __restrict__ out) {
    __shared__ float s0[D_];
    __shared__ float s1[D_];
    for (int i = threadIdx.x; i < D_; i += 256) { s0[i] = hf[i]; s1[i] = hf[D_ + i]; }
    __syncthreads();
    int vcol = blockIdx.x * 256 + threadIdx.x;
    float a0 = 0.f, a1 = 0.f;
    #pragma unroll 4
    for (int d = 0; d < D_; d++) {
        float wv = W[(size_t)d * V_ + vcol];
        a0 += s0[d] * wv;
        a1 += s1[d] * wv;
    }
    float bb = hb[vcol];
    out[vcol]      = a0 + bb;
    out[V_ + vcol] = a1 + bb;
}

// ---------------- launch --------------------------------------------------
extern "C" void kernel_launch(void* const* d_in, const int* in_sizes, int n_in,
                              void* d_out, int out_size) {
    const int*   idx    = (const int*)  d_in[0];
    const float* tok    = (const float*)d_in[1];
    const float* pos    = (const float*)d_in[2];
    const float* ln1w   = (const float*)d_in[3];
    const float* ln1b   = (const float*)d_in[4];
    const float* qw     = (const float*)d_in[5];
    const float* qb     = (const float*)d_in[6];
    const float* kw     = (const float*)d_in[7];
    const float* kbi    = (const float*)d_in[8];
    const float* vw     = (const float*)d_in[9];
    const float* vb     = (const float*)d_in[10];
    const float* ow     = (const float*)d_in[11];
    const float* ob     = (const float*)d_in[12];
    const float* ln2w   = (const float*)d_in[13];
    const float* ln2b   = (const float*)d_in[14];
    const float* f1w    = (const float*)d_in[15];
    const float* f1b    = (const float*)d_in[16];
    const float* f2w    = (const float*)d_in[17];
    const float* f2b    = (const float*)d_in[18];
    const float* lnfw   = (const float*)d_in[19];
    const float* lnfb   = (const float*)d_in[20];
    const float* headw  = (const float*)d_in[21];
    const float* headb  = (const float*)d_in[22];

    float *x, *hf;
    __half *wqkv, *wo, *wf1, *wf2, *q, *k, *v, *hh, *oh, *ffh;
    cudaGetSymbolAddress((void**)&x,    g_x);
    cudaGetSymbolAddress((void**)&hf,   g_hf);
    cudaGetSymbolAddress((void**)&wqkv, g_wqkv);
    cudaGetSymbolAddress((void**)&wo,   g_wo);
    cudaGetSymbolAddress((void**)&wf1,  g_wf1);
    cudaGetSymbolAddress((void**)&wf2,  g_wf2);
    cudaGetSymbolAddress((void**)&q,    g_q);
    cudaGetSymbolAddress((void**)&k,    g_k);
    cudaGetSymbolAddress((void**)&v,    g_v);
    cudaGetSymbolAddress((void**)&hh,   g_hh);
    cudaGetSymbolAddress((void**)&oh,   g_oh);
    cudaGetSymbolAddress((void**)&ffh,  g_ffh);

    const int GS128 = 3 * (128 * 80 + B_TILE);   // 56832
    const int GS64  = 3 * (64 * 80 + B_TILE);    // 41472
    cudaFuncSetAttribute(gemm_tc<0, 128>, cudaFuncAttributeMaxDynamicSharedMemorySize, GS128);
    cudaFuncSetAttribute(gemm_tc<1, 64>,  cudaFuncAttributeMaxDynamicSharedMemorySize, GS64);
    cudaFuncSetAttribute(gemm_tc<2, 128>, cudaFuncAttributeMaxDynamicSharedMemorySize, GS128);
    cudaFuncSetAttribute(attn_k, cudaFuncAttributeMaxDynamicSharedMemorySize, ATT_SMEM);

    const long MEG = 1024 * 1024;
    dim3 gQKV(24, 16), gDD(8, 32), gF1(32, 16);
    dim3 gAt(T_ / 64, B_ * H_);

    embed_k<<<M_, 256>>>(idx, tok, pos);
    convqkv<<<dim3(1024, L_), 256>>>(qw, 0,    wqkv);
    convqkv<<<dim3(1024, L_), 256>>>(kw, 1024, wqkv);
    convqkv<<<dim3(1024, L_), 256>>>(vw, 2048, wqkv);
    ln_k<<<M_, 256>>>(x, D_, ln1w, ln1b, hh, nullptr);
    gemm_tc<0, 128><<<gQKV, 256, GS128>>>(hh, wqkv, qb, kbi, vb, nullptr,
                                          nullptr, nullptr, q, k, v, D_, 3 * D_, 0);
    convw1<<<(L_ * MEG) / 2048, 256>>>(ow,  wo);
    convw1<<<(L_ * 4 * MEG) / 2048, 256>>>(f1w, wf1);
    convw1<<<(L_ * 4 * MEG) / 2048, 256>>>(f2w, wf2);

    for (int l = 0; l < L_; l++) {
        size_t wq3 = (size_t)l * 3 * MEG;
        size_t wdd = (size_t)l * MEG;
        size_t wff = (size_t)l * 4 * MEG;

        if (l > 0) {
            ln_k<<<M_, 256>>>(x, D_, ln1w + l * D_, ln1b + l * D_, hh, nullptr);
            gemm_tc<0, 128><<<gQKV, 256, GS128>>>(hh, wqkv + wq3,
                                                  qb + l * D_, kbi + l * D_, vb + l * D_,
                                                  nullptr, nullptr, nullptr,
                                                  q, k, v, D_, 3 * D_, 0);
        }

        attn_k<<<gAt, 128, ATT_SMEM>>>(q, k, v, oh);

        gemm_tc<1, 64><<<gDD, 256, GS64>>>(oh, wo + wdd,
                                           ob + l * D_, nullptr, nullptr, x,
                                           x, nullptr, nullptr, nullptr, nullptr,
                                           D_, D_, D_);

        ln_k<<<M_, 256>>>(x, D_, ln2w + l * D_, ln2b + l * D_, hh, nullptr);

        gemm_tc<2, 128><<<gF1, 256, GS128>>>(hh, wf1 + wff,
                                             f1b + l * FF_, nullptr, nullptr, nullptr,
                                             nullptr, ffh, nullptr, nullptr, nullptr,
                                             D_, FF_, FF_);

        gemm_tc<1, 64><<<gDD, 256, GS64>>>(ffh, wf2 + wff,
                                           f2b + l * D_, nullptr, nullptr, x,
                                           x, nullptr, nullptr, nullptr, nullptr,
                                           FF_, D_, D_);
    }

    ln_k<<<B_, 256>>>(x + (size_t)(T_ - 1) * D_, (long)T_ * D_, lnfw, lnfb,
                      nullptr, hf);

    head_k<<<V_ / 256, 256>>>(hf, headw, headb, (float*)d_out);
}